// round 14
// baseline (speedup 1.0000x reference)
#include <cuda_runtime.h>
#include <cuda_fp16.h>
#include <cstdint>
#include <math.h>

#define TOK 8192
#define EMB 512
#define SEQ 2048

// ---------------------------------------------------------------------------
// Scratch (__device__ globals: no allocs allowed)
// ---------------------------------------------------------------------------
__device__ float g_ctx[TOK * EMB];
__device__ float g_x[TOK * EMB];

// fp16 activations
__device__ __half g_xh[TOK * 256];
__device__ __half g_hidh[TOK * 1536];     // QKV layer-1 hidden
__device__ __half g_qkvh[TOK * 1536];     // q|k|v concat
__device__ __half g_ah[TOK * 1024];       // FFN hidden
__device__ __half g_bh[TOK * 512];        // LN1 out

// fp16 transposed weights, stored [N][K]; QKV groups contiguous
__device__ __half g_w1h[3][512 * 256];    // => [1536][256]
__device__ __half g_w2h[3][512 * 512];    // => [1536][512]
__device__ __half g_f1h[1024 * 512];
__device__ __half g_f2h[512 * 1024];
__device__ float g_b1cat[1536], g_b2cat[1536];

// ---------------------------------------------------------------------------
// Family-portable PTX helpers
// ---------------------------------------------------------------------------
__device__ __forceinline__ uint32_t smem_u32(const void* p) {
    uint32_t a;
    asm("{ .reg .u64 t; cvta.to.shared.u64 t, %1; cvt.u32.u64 %0, t; }" : "=r"(a) : "l"(p));
    return a;
}
__device__ __forceinline__ void cp16(uint32_t dst, const void* src) {
    asm volatile("cp.async.cg.shared.global [%0], [%1], 16;" :: "r"(dst), "l"(src) : "memory");
}
__device__ __forceinline__ void cp_commit() {
    asm volatile("cp.async.commit_group;" ::: "memory");
}
__device__ __forceinline__ void ldsm_x4(uint32_t* r, uint32_t addr) {
    asm volatile("ldmatrix.sync.aligned.m8n8.x4.shared.b16 {%0,%1,%2,%3}, [%4];"
                 : "=r"(r[0]), "=r"(r[1]), "=r"(r[2]), "=r"(r[3]) : "r"(addr));
}
__device__ __forceinline__ void ldsm_x4_t(uint32_t* r, uint32_t addr) {
    asm volatile("ldmatrix.sync.aligned.m8n8.x4.trans.shared.b16 {%0,%1,%2,%3}, [%4];"
                 : "=r"(r[0]), "=r"(r[1]), "=r"(r[2]), "=r"(r[3]) : "r"(addr));
}
__device__ __forceinline__ void mma16816(float* c, const uint32_t* a, const uint32_t* b) {
    asm volatile("mma.sync.aligned.m16n8k16.row.col.f32.f16.f16.f32 "
                 "{%0,%1,%2,%3}, {%4,%5,%6,%7}, {%8,%9}, {%0,%1,%2,%3};"
                 : "+f"(c[0]), "+f"(c[1]), "+f"(c[2]), "+f"(c[3])
                 : "r"(a[0]), "r"(a[1]), "r"(a[2]), "r"(a[3]), "r"(b[0]), "r"(b[1]));
}
__device__ __forceinline__ uint32_t ex2_h2(uint32_t x) {
    uint32_t r;
    asm("ex2.approx.f16x2 %0, %1;" : "=r"(r) : "r"(x));
    return r;
}

// ---------------------------------------------------------------------------
// Single fused prep kernel
// ---------------------------------------------------------------------------
#define W_TOTAL 2228224
#define X_TOTAL (TOK * 256)
#define PREP_TOTAL (W_TOTAL + X_TOTAL + 3072)

__global__ void prep_all(
    const float* x_in,
    const float* qW1, const float* kW1, const float* vW1,
    const float* qW2, const float* kW2, const float* vW2,
    const float* fW1, const float* fW2,
    const float* qb1, const float* kb1, const float* vb1,
    const float* qb2, const float* kb2, const float* vb2,
    __half* w1h, __half* w2h, __half* f1h, __half* f2h,
    __half* xh, float* b1cat, float* b2cat)
{
    int idx = blockIdx.x * blockDim.x + threadIdx.x;
    if (idx < W_TOTAL) {
        const float* src; __half* dh; int K, N, local;
        if (idx < 393216) {
            int p = idx / 131072; local = idx - p * 131072;
            src = (p == 0) ? qW1 : (p == 1) ? kW1 : vW1;
            dh = w1h + p * 131072; K = 256; N = 512;
        } else if (idx < 1179648) {
            int r = idx - 393216; int p = r / 262144; local = r - p * 262144;
            src = (p == 0) ? qW2 : (p == 1) ? kW2 : vW2;
            dh = w2h + p * 262144; K = 512; N = 512;
        } else if (idx < 1703936) {
            local = idx - 1179648; src = fW1; dh = f1h; K = 512; N = 1024;
        } else {
            local = idx - 1703936; src = fW2; dh = f2h; K = 1024; N = 512;
        }
        int k = local / N, n = local - k * N;
        dh[(size_t)n * K + k] = __float2half_rn(src[local]);
    } else if (idx < W_TOTAL + X_TOTAL) {
        int i = idx - W_TOTAL;
        xh[i] = __float2half_rn(x_in[i]);
    } else if (idx < PREP_TOTAL) {
        int i = idx - W_TOTAL - X_TOTAL;
        if (i < 1536) {
            int p = i >> 9, c = i & 511;
            b1cat[i] = (p == 0 ? qb1 : p == 1 ? kb1 : vb1)[c];
        } else {
            int j = i - 1536, p = j >> 9, c = j & 511;
            b2cat[j] = (p == 0 ? qb2 : p == 1 ? kb2 : vb2)[c];
        }
    }
}

// ---------------------------------------------------------------------------
// HMMA fp16 GEMM (proven round-13 config: BK=64, KPAD=72, 3-stage)
// ---------------------------------------------------------------------------
#define KPAD 72
#define TILE_SM (128 * KPAD)
#define STAGE_SM (2 * TILE_SM)
#define GSMEM (3 * STAGE_SM * 2)        // 110592 B

__global__ void __launch_bounds__(256, 2) hmma_gemm(
    const __half* __restrict__ Ah, int lda, int ashift,
    const __half* __restrict__ Bh,
    const float* __restrict__ bias, float* __restrict__ Cf, int cf_ncols,
    __half* __restrict__ Ch,
    int N, int K, int relu)
{
    extern __shared__ __half sm[];
    const uint32_t smb = smem_u32(sm);
    const int tid = threadIdx.x;
    const int wid = tid >> 5, lane = tid & 31;
    const int bm = blockIdx.y * 128, bn = blockIdx.x * 128;
    const int wm = (wid >> 2) * 64, wn = (wid & 3) * 32;
    const int aoff = (bn >> 9) * ashift;

    float acc[4][4][4];
#pragma unroll
    for (int mt = 0; mt < 4; mt++)
#pragma unroll
        for (int nt = 0; nt < 4; nt++)
#pragma unroll
            for (int r = 0; r < 4; r++) acc[mt][nt][r] = 0.f;

    const int nch = K >> 6;

    auto issue_loads = [&](int ck, int s) {
        const int koff = ck * 64;
        const __half* a_ = Ah + (size_t)bm * lda + aoff + koff;
        const __half* b_ = Bh + (size_t)bn * K + koff;
#pragma unroll
        for (int i = 0; i < 4; i++) {
            int idx = tid + i * 256;
            int r = idx >> 3, c16 = idx & 7;
            uint32_t d0 = smb + (uint32_t)(s * STAGE_SM + r * KPAD + c16 * 8) * 2;
            cp16(d0,               a_ + (size_t)r * lda + c16 * 8);
            cp16(d0 + TILE_SM * 2, b_ + (size_t)r * K + c16 * 8);
        }
        cp_commit();
    };

    issue_loads(0, 0);
    if (nch > 1) issue_loads(1, 1);

    const int arow = (lane & 15);
    const int acol8 = (lane >> 4) * 8;
    const int brow = ((lane >> 4) & 1) * 8 + (lane & 7);
    const int bcol8 = ((lane >> 3) & 1) * 8;

    int s = 0;
    for (int ck = 0; ck < nch; ck++) {
        if (ck < nch - 1) {
            asm volatile("cp.async.wait_group 1;" ::: "memory");
        } else {
            asm volatile("cp.async.wait_group 0;" ::: "memory");
        }
        __syncthreads();
        if (ck + 2 < nch) {
            int s2 = s + 2; if (s2 >= 3) s2 -= 3;
            issue_loads(ck + 2, s2);
        }

        const uint32_t aA = smb + (uint32_t)(s * STAGE_SM) * 2;
        const uint32_t bB = aA + (uint32_t)TILE_SM * 2;

#pragma unroll
        for (int k16 = 0; k16 < 4; k16++) {
            uint32_t fa[4][4], fb[2][4];
#pragma unroll
            for (int mt = 0; mt < 4; mt++) {
                uint32_t off = (uint32_t)((wm + mt * 16 + arow) * KPAD + k16 * 16 + acol8) * 2;
                ldsm_x4(fa[mt], aA + off);
            }
#pragma unroll
            for (int p = 0; p < 2; p++) {
                uint32_t off = (uint32_t)((wn + p * 16 + brow) * KPAD + k16 * 16 + bcol8) * 2;
                ldsm_x4(fb[p], bB + off);
            }
#pragma unroll
            for (int mt = 0; mt < 4; mt++) {
#pragma unroll
                for (int nt = 0; nt < 4; nt++) {
                    mma16816(acc[mt][nt], fa[mt], &fb[nt >> 1][(nt & 1) * 2]);
                }
            }
        }
        if (++s == 3) s = 0;
    }

    const int gid = lane >> 2, tig = lane & 3;
#pragma unroll
    for (int mt = 0; mt < 4; mt++) {
#pragma unroll
        for (int nt = 0; nt < 4; nt++) {
            const int c0 = bn + wn + nt * 8 + tig * 2;
            const float bb0 = __ldg(&bias[c0]), bb1 = __ldg(&bias[c0 + 1]);
#pragma unroll
            for (int half = 0; half < 2; half++) {
                const int r = bm + wm + mt * 16 + gid + half * 8;
                float v0 = acc[mt][nt][half * 2 + 0] + bb0;
                float v1 = acc[mt][nt][half * 2 + 1] + bb1;
                if (relu) { v0 = fmaxf(v0, 0.f); v1 = fmaxf(v1, 0.f); }
                if (Cf && c0 < cf_ncols)
                    *reinterpret_cast<float2*>(Cf + (size_t)r * cf_ncols + c0) = make_float2(v0, v1);
                if (Ch) {
                    __half2 hh = __floats2half2_rn(v0, v1);
                    *reinterpret_cast<__half2*>(Ch + (size_t)r * N + c0) = hh;
                }
            }
        }
    }
}

// ---------------------------------------------------------------------------
// HMMA flash attention v7: 128 q-rows / 8 warps / 256 threads, 2 CTAs/SM
// (same 16 warps/SM as v5 but HALF the CTAs: K/V smem-fill + L2 traffic
// halve; per-warp MMA structure identical -> bit-identical numerics).
// Single barrier per iteration (loads issued after the top barrier).
// ---------------------------------------------------------------------------
#define FPITCH 72
#define FTILE (64 * FPITCH)
#define FQTILE (128 * FPITCH)
#define FKV0 FQTILE
#define FSTAGE (2 * FTILE)                     // K, V
#define FSMEM ((FQTILE + 2 * FSTAGE) * 2)      // 55296 bytes
#define LDQ 1536

__global__ void __launch_bounds__(256, 2) flash_hmma(
    const __half* __restrict__ QKV, float* __restrict__ O)
{
    extern __shared__ __half fsm[];
    const uint32_t smb = smem_u32(fsm);
    const int tid = threadIdx.x, wid = tid >> 5, lane = tid & 31;
    const int qt = blockIdx.x, h = blockIdx.y, b = blockIdx.z;
    const int qrow0 = b * SEQ + qt * 128;
    const int col0 = h * 64;
    const float CEXP = 0.044194173824159216f * 1.4426950408889634f;
    const float FOFF = 4.0f * 1.4426950408889634f;

    // Load Q tile [128 x 64]
#pragma unroll
    for (int i = 0; i < 4; i++) {
        int idx = tid + i * 256;               // 0..1023
        int r = idx >> 3, ch = idx & 7;
        uint4 v = *reinterpret_cast<const uint4*>(QKV + (size_t)(qrow0 + r) * LDQ + col0 + ch * 8);
        *reinterpret_cast<uint4*>(fsm + r * FPITCH + ch * 8) = v;
    }
    __syncthreads();

    const int warpm = wid * 16;                // 8 warps x 16 rows
    const int arow = lane & 15, acol8 = (lane >> 4) * 8;
    uint32_t qf[4][4];
#pragma unroll
    for (int kk = 0; kk < 4; kk++) {
        uint32_t off = (uint32_t)((warpm + arow) * FPITCH + kk * 16 + acol8) * 2;
        ldsm_x4(qf[kk], smb + off);
    }

    auto load_kv = [&](int it, int s) {
        const __half* base = QKV + (size_t)(b * SEQ + it * 64) * LDQ + col0;
        const uint32_t stg = (uint32_t)(FKV0 + s * FSTAGE);
#pragma unroll
        for (int i = 0; i < 4; i++) {
            int idx = tid + i * 256;           // 0..1023: K, V tiles
            int t = idx >> 9, r = (idx >> 3) & 63, ch = idx & 7;
            uint32_t dst = smb + (stg + (uint32_t)(t * FTILE + r * FPITCH + ch * 8)) * 2;
            cp16(dst, base + (size_t)r * LDQ + (t ? 1024 : 512) + ch * 8);
        }
        cp_commit();
    };

    float lacc[4] = {0.f, 0.f, 0.f, 0.f};
    float o[8][4];
#pragma unroll
    for (int nt = 0; nt < 8; nt++)
#pragma unroll
        for (int j = 0; j < 4; j++) o[nt][j] = 0.f;

    const uint32_t ones2[2] = {0x3C003C00u, 0x3C003C00u};

    const int brow = (lane & 7) + ((lane >> 4) & 1) * 8;
    const int bcol8 = ((lane >> 3) & 1) * 8;
    const int vrow = (lane & 7) + ((lane >> 3) & 1) * 8;
    const int vcol8 = ((lane >> 4) & 1) * 8;

    load_kv(0, 0);

    for (int it = 0; it < SEQ / 64; it++) {
        const int s = it & 1;
        asm volatile("cp.async.wait_group 0;" ::: "memory");
        __syncthreads();                       // single barrier per iter
        if (it + 1 < SEQ / 64) load_kv(it + 1, s ^ 1);

        const uint32_t stg = smb + (uint32_t)(FKV0 + s * FSTAGE) * 2;
        const uint32_t kb = stg, vb = stg + FTILE * 2;

        float sacc[8][4];
#pragma unroll
        for (int nt = 0; nt < 8; nt++)
#pragma unroll
            for (int j = 0; j < 4; j++) sacc[nt][j] = 0.f;

#pragma unroll
        for (int kk = 0; kk < 4; kk++) {
#pragma unroll
            for (int np = 0; np < 4; np++) {
                uint32_t bh[4];
                uint32_t off = (uint32_t)((np * 16 + brow) * FPITCH + kk * 16 + bcol8) * 2;
                ldsm_x4(bh, kb + off);
                mma16816(sacc[2 * np],     qf[kk], bh);
                mma16816(sacc[2 * np + 1], qf[kk], bh + 2);
            }
        }

        uint32_t pf[4][4];
#pragma unroll
        for (int np = 0; np < 4; np++) {
#pragma unroll
            for (int half = 0; half < 2; half++) {
                const int nt = 2 * np + half;
                __half2 x01 = __floats2half2_rn(fmaf(sacc[nt][0], CEXP, -FOFF),
                                                fmaf(sacc[nt][1], CEXP, -FOFF));
                __half2 x23 = __floats2half2_rn(fmaf(sacc[nt][2], CEXP, -FOFF),
                                                fmaf(sacc[nt][3], CEXP, -FOFF));
                pf[np][half * 2 + 0] = ex2_h2(*reinterpret_cast<uint32_t*>(&x01));
                pf[np][half * 2 + 1] = ex2_h2(*reinterpret_cast<uint32_t*>(&x23));
            }
        }

#pragma unroll
        for (int kk = 0; kk < 4; kk++) {
            mma16816(lacc, pf[kk], ones2);
#pragma unroll
            for (int dp = 0; dp < 4; dp++) {
                uint32_t vh[4];
                uint32_t off = (uint32_t)((kk * 16 + vrow) * FPITCH + dp * 16 + vcol8) * 2;
                ldsm_x4_t(vh, vb + off);
                mma16816(o[2 * dp],     pf[kk], vh);
                mma16816(o[2 * dp + 1], pf[kk], vh + 2);
            }
        }
    }

    const float inv0 = 1.f / lacc[0], inv1 = 1.f / lacc[2];
    const int r0 = qrow0 + warpm + (lane >> 2), r1 = r0 + 8;
#pragma unroll
    for (int nt = 0; nt < 8; nt++) {
        const int c = col0 + nt * 8 + (lane & 3) * 2;
        *reinterpret_cast<float2*>(O + (size_t)r0 * EMB + c) = make_float2(o[nt][0] * inv0, o[nt][1] * inv0);
        *reinterpret_cast<float2*>(O + (size_t)r1 * EMB + c) = make_float2(o[nt][2] * inv1, o[nt][3] * inv1);
    }
}

// ---------------------------------------------------------------------------
// Fused residual + LayerNorm, float4-vectorized; residual fp32 or fp16-strided
// ---------------------------------------------------------------------------
__global__ void ln_kernel(const float* __restrict__ A,
                          const float* __restrict__ BresF,
                          const __half* __restrict__ BresH, int bres_ld,
                          const float* __restrict__ g, const float* __restrict__ beta,
                          float* __restrict__ out, __half* __restrict__ oh)
{
    const int row = blockIdx.x;
    const int t = threadIdx.x;  // 128
    const size_t base = (size_t)row * 128 + t;
    float4 a = reinterpret_cast<const float4*>(A)[base];
    float4 bq;
    if (BresF) {
        bq = reinterpret_cast<const float4*>(BresF)[base];
    } else {
        uint2 raw = *reinterpret_cast<const uint2*>(BresH + (size_t)row * bres_ld + t * 4);
        float2 f0 = __half22float2(*reinterpret_cast<__half2*>(&raw.x));
        float2 f1 = __half22float2(*reinterpret_cast<__half2*>(&raw.y));
        bq = make_float4(f0.x, f0.y, f1.x, f1.y);
    }
    float4 v = make_float4(a.x + bq.x, a.y + bq.y, a.z + bq.z, a.w + bq.w);

    __shared__ float rsum[4], rsq[4];
    float s1 = v.x + v.y + v.z + v.w;
    float s2 = v.x * v.x + v.y * v.y + v.z * v.z + v.w * v.w;
#pragma unroll
    for (int off = 16; off; off >>= 1) {
        s1 += __shfl_xor_sync(0xffffffffu, s1, off);
        s2 += __shfl_xor_sync(0xffffffffu, s2, off);
    }
    if ((t & 31) == 0) { rsum[t >> 5] = s1; rsq[t >> 5] = s2; }
    __syncthreads();
    s1 = rsum[0] + rsum[1] + rsum[2] + rsum[3];
    s2 = rsq[0] + rsq[1] + rsq[2] + rsq[3];
    float mu = s1 * (1.f / EMB);
    float var = s2 * (1.f / EMB) - mu * mu;
    float inv = rsqrtf(var + 1e-5f);

    float4 gg = reinterpret_cast<const float4*>(g)[t];
    float4 bb = reinterpret_cast<const float4*>(beta)[t];
    float4 y = make_float4((v.x - mu) * inv * gg.x + bb.x,
                           (v.y - mu) * inv * gg.y + bb.y,
                           (v.z - mu) * inv * gg.z + bb.z,
                           (v.w - mu) * inv * gg.w + bb.w);
    reinterpret_cast<float4*>(out)[base] = y;
    if (oh) {
        __half2 h0 = __floats2half2_rn(y.x, y.y);
        __half2 h1 = __floats2half2_rn(y.z, y.w);
        uint2 pk = make_uint2(*reinterpret_cast<uint32_t*>(&h0), *reinterpret_cast<uint32_t*>(&h1));
        reinterpret_cast<uint2*>(oh)[base] = pk;
    }
}

// ---------------------------------------------------------------------------
// Launch
// ---------------------------------------------------------------------------
extern "C" void kernel_launch(void* const* d_in, const int* in_sizes, int n_in,
                              void* d_out, int out_size)
{
    (void)in_sizes; (void)n_in; (void)out_size;

    const float* x_in = (const float*)d_in[0];
    const float* qW1 = (const float*)d_in[1];  const float* qb1 = (const float*)d_in[2];
    const float* qW2 = (const float*)d_in[3];  const float* qb2 = (const float*)d_in[4];
    const float* kW1 = (const float*)d_in[5];  const float* kb1 = (const float*)d_in[6];
    const float* kW2 = (const float*)d_in[7];  const float* kb2 = (const float*)d_in[8];
    const float* vW1 = (const float*)d_in[9];  const float* vb1 = (const float*)d_in[10];
    const float* vW2 = (const float*)d_in[11]; const float* vb2 = (const float*)d_in[12];
    const float* fW1 = (const float*)d_in[13]; const float* fb1 = (const float*)d_in[14];
    const float* fW2 = (const float*)d_in[15]; const float* fb2 = (const float*)d_in[16];
    const float* ln1g = (const float*)d_in[17]; const float* ln1b = (const float*)d_in[18];
    const float* ln2g = (const float*)d_in[19]; const float* ln2b = (const float*)d_in[20];
    float* out = (float*)d_out;

    float *pctx, *px, *pb1c, *pb2c;
    cudaGetSymbolAddress((void**)&pctx, g_ctx);
    cudaGetSymbolAddress((void**)&px, g_x);
    cudaGetSymbolAddress((void**)&pb1c, g_b1cat);
    cudaGetSymbolAddress((void**)&pb2c, g_b2cat);
    __half *xh, *hidh, *qkvh, *ah, *bh;
    cudaGetSymbolAddress((void**)&xh, g_xh);
    cudaGetSymbolAddress((void**)&hidh, g_hidh);
    cudaGetSymbolAddress((void**)&qkvh, g_qkvh);
    cudaGetSymbolAddress((void**)&ah, g_ah);
    cudaGetSymbolAddress((void**)&bh, g_bh);
    __half *w1h, *w2h, *f1h, *f2h;
    cudaGetSymbolAddress((void**)&w1h, g_w1h);
    cudaGetSymbolAddress((void**)&w2h, g_w2h);
    cudaGetSymbolAddress((void**)&f1h, g_f1h);
    cudaGetSymbolAddress((void**)&f2h, g_f2h);

    cudaFuncSetAttribute(hmma_gemm, cudaFuncAttributeMaxDynamicSharedMemorySize, GSMEM);
    cudaFuncSetAttribute(flash_hmma, cudaFuncAttributeMaxDynamicSharedMemorySize, FSMEM);

    // One fused prep launch
    prep_all<<<(PREP_TOTAL + 255) / 256, 256>>>(
        x_in, qW1, kW1, vW1, qW2, kW2, vW2, fW1, fW2,
        qb1, kb1, vb1, qb2, kb2, vb2,
        w1h, w2h, f1h, f2h, xh, pb1c, pb2c);

    // Merged QKV layer-1
    hmma_gemm<<<dim3(12, 64), 256, GSMEM>>>(xh, 256, 0, w1h, pb1c,
                                            (float*)nullptr, 0, hidh, 1536, 256, 1);
    // Merged QKV layer-2 -> qkv fp16 (q residual read from here later)
    hmma_gemm<<<dim3(12, 64), 256, GSMEM>>>(hidh, 1536, 512, w2h, pb2c,
                                            (float*)nullptr, 0, qkvh, 1536, 512, 0);

    // Attention (128 q-rows, 8 warps, 2 CTAs/SM)
    flash_hmma<<<dim3(SEQ / 128, 8, 4), 256, FSMEM>>>(qkvh, pctx);

    // x = LN(ctx + q[fp16 from qkv]), fp16 out for FFN
    ln_kernel<<<TOK, 128>>>(pctx, (float*)nullptr, qkvh, 1536, ln1g, ln1b, px, bh);

    // FFN
    hmma_gemm<<<dim3(8, 64), 256, GSMEM>>>(bh, 512, 0, f1h, fb1,
                                           (float*)nullptr, 0, ah, 1024, 512, 1);
    hmma_gemm<<<dim3(4, 64), 256, GSMEM>>>(ah, 1024, 0, f2h, fb2,
                                           pctx, 512, (__half*)nullptr, 512, 1024, 0);

    // out = LN(x + ff)
    ln_kernel<<<TOK, 128>>>(px, pctx, (const __half*)nullptr, 0, ln2g, ln2b, out, (__half*)nullptr);
}

// round 15
// speedup vs baseline: 1.0674x; 1.0674x over previous
#include <cuda_runtime.h>
#include <cuda_fp16.h>
#include <cstdint>
#include <math.h>

#define TOK 8192
#define EMB 512
#define SEQ 2048

// ---------------------------------------------------------------------------
// Scratch (__device__ globals: no allocs allowed)
// ---------------------------------------------------------------------------
__device__ float g_ctx[TOK * EMB];
__device__ float g_x[TOK * EMB];

// fp16 activations
__device__ __half g_xh[TOK * 256];
__device__ __half g_hidh[TOK * 1536];     // QKV layer-1 hidden
__device__ __half g_qkvh[TOK * 1536];     // q|k|v concat
__device__ __half g_ah[TOK * 1024];       // FFN hidden
__device__ __half g_bh[TOK * 512];        // LN1 out

// fp16 transposed weights, stored [N][K]; QKV groups contiguous
__device__ __half g_w1h[3][512 * 256];    // => [1536][256]
__device__ __half g_w2h[3][512 * 512];    // => [1536][512]
__device__ __half g_f1h[1024 * 512];
__device__ __half g_f2h[512 * 1024];
__device__ float g_b1cat[1536], g_b2cat[1536];

// ---------------------------------------------------------------------------
// Family-portable PTX helpers
// ---------------------------------------------------------------------------
__device__ __forceinline__ uint32_t smem_u32(const void* p) {
    uint32_t a;
    asm("{ .reg .u64 t; cvta.to.shared.u64 t, %1; cvt.u32.u64 %0, t; }" : "=r"(a) : "l"(p));
    return a;
}
__device__ __forceinline__ void cp16(uint32_t dst, const void* src) {
    asm volatile("cp.async.cg.shared.global [%0], [%1], 16;" :: "r"(dst), "l"(src) : "memory");
}
__device__ __forceinline__ void cp_commit() {
    asm volatile("cp.async.commit_group;" ::: "memory");
}
__device__ __forceinline__ void ldsm_x4(uint32_t* r, uint32_t addr) {
    asm volatile("ldmatrix.sync.aligned.m8n8.x4.shared.b16 {%0,%1,%2,%3}, [%4];"
                 : "=r"(r[0]), "=r"(r[1]), "=r"(r[2]), "=r"(r[3]) : "r"(addr));
}
__device__ __forceinline__ void ldsm_x4_t(uint32_t* r, uint32_t addr) {
    asm volatile("ldmatrix.sync.aligned.m8n8.x4.trans.shared.b16 {%0,%1,%2,%3}, [%4];"
                 : "=r"(r[0]), "=r"(r[1]), "=r"(r[2]), "=r"(r[3]) : "r"(addr));
}
__device__ __forceinline__ void mma16816(float* c, const uint32_t* a, const uint32_t* b) {
    asm volatile("mma.sync.aligned.m16n8k16.row.col.f32.f16.f16.f32 "
                 "{%0,%1,%2,%3}, {%4,%5,%6,%7}, {%8,%9}, {%0,%1,%2,%3};"
                 : "+f"(c[0]), "+f"(c[1]), "+f"(c[2]), "+f"(c[3])
                 : "r"(a[0]), "r"(a[1]), "r"(a[2]), "r"(a[3]), "r"(b[0]), "r"(b[1]));
}
__device__ __forceinline__ uint32_t ex2_h2(uint32_t x) {
    uint32_t r;
    asm("ex2.approx.f16x2 %0, %1;" : "=r"(r) : "r"(x));
    return r;
}

// ---------------------------------------------------------------------------
// Prep A: coalesced 32x32 smem-tile transpose+convert for all weights.
// Old path stored 2B elements at 512B-2KB stride (32x write amplification).
// ---------------------------------------------------------------------------
__global__ void __launch_bounds__(256) transpose_w(
    const float* qW1, const float* kW1, const float* vW1,
    const float* qW2, const float* kW2, const float* vW2,
    const float* fW1, const float* fW2,
    __half* w1h, __half* w2h, __half* f1h, __half* f2h)
{
    int bid = blockIdx.x;                 // 0..2175
    const float* src; __half* dst; int K, N, tk, tn;
    if (bid < 384) {                      // 3 x W1: K=256,N=512 -> 8x16=128 tiles
        int p = bid / 128, r = bid - p * 128;
        src = (p == 0) ? qW1 : (p == 1) ? kW1 : vW1;
        dst = w1h + p * 131072; K = 256; N = 512; tk = r >> 4; tn = r & 15;
    } else if (bid < 1152) {              // 3 x W2: 512x512 -> 16x16=256 tiles
        int r = bid - 384; int p = r / 256; r -= p * 256;
        src = (p == 0) ? qW2 : (p == 1) ? kW2 : vW2;
        dst = w2h + p * 262144; K = 512; N = 512; tk = r >> 4; tn = r & 15;
    } else if (bid < 1664) {              // F1: 512x1024 -> 16x32=512 tiles
        int r = bid - 1152;
        src = fW1; dst = f1h; K = 512; N = 1024; tk = r >> 5; tn = r & 31;
    } else {                              // F2: 1024x512 -> 32x16=512 tiles
        int r = bid - 1664;
        src = fW2; dst = f2h; K = 1024; N = 512; tk = r >> 4; tn = r & 15;
    }
    __shared__ __half tile[32][34];       // pitch 34 halves: conflict-free writes
    const int tx = threadIdx.x & 31, ty = threadIdx.x >> 5;   // 32 x 8
    const int k0 = tk * 32, n0 = tn * 32;
#pragma unroll
    for (int j = 0; j < 4; j++) {
        int k = k0 + ty + j * 8;
        tile[tx][ty + j * 8] = __float2half_rn(src[(size_t)k * N + n0 + tx]);
    }
    __syncthreads();
#pragma unroll
    for (int j = 0; j < 4; j++) {
        int n = n0 + ty + j * 8;
        dst[(size_t)n * K + k0 + tx] = tile[ty + j * 8][tx];
    }
}

// Prep B: input convert + bias concat
#define X_TOTAL (TOK * 256)
__global__ void prep_misc(
    const float* x_in,
    const float* qb1, const float* kb1, const float* vb1,
    const float* qb2, const float* kb2, const float* vb2,
    __half* xh, float* b1cat, float* b2cat)
{
    int idx = blockIdx.x * blockDim.x + threadIdx.x;
    if (idx < X_TOTAL) {
        xh[idx] = __float2half_rn(x_in[idx]);
    } else if (idx < X_TOTAL + 3072) {
        int i = idx - X_TOTAL;
        if (i < 1536) {
            int p = i >> 9, c = i & 511;
            b1cat[i] = (p == 0 ? qb1 : p == 1 ? kb1 : vb1)[c];
        } else {
            int j = i - 1536, p = j >> 9, c = j & 511;
            b2cat[j] = (p == 0 ? qb2 : p == 1 ? kb2 : vb2)[c];
        }
    }
}

// ---------------------------------------------------------------------------
// HMMA fp16 GEMM (proven round-13 config: BK=64, KPAD=72, 3-stage)
// ---------------------------------------------------------------------------
#define KPAD 72
#define TILE_SM (128 * KPAD)
#define STAGE_SM (2 * TILE_SM)
#define GSMEM (3 * STAGE_SM * 2)        // 110592 B

__global__ void __launch_bounds__(256, 2) hmma_gemm(
    const __half* __restrict__ Ah, int lda, int ashift,
    const __half* __restrict__ Bh,
    const float* __restrict__ bias, float* __restrict__ Cf, int cf_ncols,
    __half* __restrict__ Ch,
    int N, int K, int relu)
{
    extern __shared__ __half sm[];
    const uint32_t smb = smem_u32(sm);
    const int tid = threadIdx.x;
    const int wid = tid >> 5, lane = tid & 31;
    const int bm = blockIdx.y * 128, bn = blockIdx.x * 128;
    const int wm = (wid >> 2) * 64, wn = (wid & 3) * 32;
    const int aoff = (bn >> 9) * ashift;

    float acc[4][4][4];
#pragma unroll
    for (int mt = 0; mt < 4; mt++)
#pragma unroll
        for (int nt = 0; nt < 4; nt++)
#pragma unroll
            for (int r = 0; r < 4; r++) acc[mt][nt][r] = 0.f;

    const int nch = K >> 6;

    auto issue_loads = [&](int ck, int s) {
        const int koff = ck * 64;
        const __half* a_ = Ah + (size_t)bm * lda + aoff + koff;
        const __half* b_ = Bh + (size_t)bn * K + koff;
#pragma unroll
        for (int i = 0; i < 4; i++) {
            int idx = tid + i * 256;
            int r = idx >> 3, c16 = idx & 7;
            uint32_t d0 = smb + (uint32_t)(s * STAGE_SM + r * KPAD + c16 * 8) * 2;
            cp16(d0,               a_ + (size_t)r * lda + c16 * 8);
            cp16(d0 + TILE_SM * 2, b_ + (size_t)r * K + c16 * 8);
        }
        cp_commit();
    };

    issue_loads(0, 0);
    if (nch > 1) issue_loads(1, 1);

    const int arow = (lane & 15);
    const int acol8 = (lane >> 4) * 8;
    const int brow = ((lane >> 4) & 1) * 8 + (lane & 7);
    const int bcol8 = ((lane >> 3) & 1) * 8;

    int s = 0;
    for (int ck = 0; ck < nch; ck++) {
        if (ck < nch - 1) {
            asm volatile("cp.async.wait_group 1;" ::: "memory");
        } else {
            asm volatile("cp.async.wait_group 0;" ::: "memory");
        }
        __syncthreads();
        if (ck + 2 < nch) {
            int s2 = s + 2; if (s2 >= 3) s2 -= 3;
            issue_loads(ck + 2, s2);
        }

        const uint32_t aA = smb + (uint32_t)(s * STAGE_SM) * 2;
        const uint32_t bB = aA + (uint32_t)TILE_SM * 2;

#pragma unroll
        for (int k16 = 0; k16 < 4; k16++) {
            uint32_t fa[4][4], fb[2][4];
#pragma unroll
            for (int mt = 0; mt < 4; mt++) {
                uint32_t off = (uint32_t)((wm + mt * 16 + arow) * KPAD + k16 * 16 + acol8) * 2;
                ldsm_x4(fa[mt], aA + off);
            }
#pragma unroll
            for (int p = 0; p < 2; p++) {
                uint32_t off = (uint32_t)((wn + p * 16 + brow) * KPAD + k16 * 16 + bcol8) * 2;
                ldsm_x4(fb[p], bB + off);
            }
#pragma unroll
            for (int mt = 0; mt < 4; mt++) {
#pragma unroll
                for (int nt = 0; nt < 4; nt++) {
                    mma16816(acc[mt][nt], fa[mt], &fb[nt >> 1][(nt & 1) * 2]);
                }
            }
        }
        if (++s == 3) s = 0;
    }

    const int gid = lane >> 2, tig = lane & 3;
#pragma unroll
    for (int mt = 0; mt < 4; mt++) {
#pragma unroll
        for (int nt = 0; nt < 4; nt++) {
            const int c0 = bn + wn + nt * 8 + tig * 2;
            const float bb0 = __ldg(&bias[c0]), bb1 = __ldg(&bias[c0 + 1]);
#pragma unroll
            for (int half = 0; half < 2; half++) {
                const int r = bm + wm + mt * 16 + gid + half * 8;
                float v0 = acc[mt][nt][half * 2 + 0] + bb0;
                float v1 = acc[mt][nt][half * 2 + 1] + bb1;
                if (relu) { v0 = fmaxf(v0, 0.f); v1 = fmaxf(v1, 0.f); }
                if (Cf && c0 < cf_ncols)
                    *reinterpret_cast<float2*>(Cf + (size_t)r * cf_ncols + c0) = make_float2(v0, v1);
                if (Ch) {
                    __half2 hh = __floats2half2_rn(v0, v1);
                    *reinterpret_cast<__half2*>(Ch + (size_t)r * N + c0) = hh;
                }
            }
        }
    }
}

// ---------------------------------------------------------------------------
// HMMA flash attention — EXACT round-11/13 v5 (proven 99us, 16 warps/SM)
// ---------------------------------------------------------------------------
#define FPITCH 72
#define FTILE (64 * FPITCH)
#define FKV0 FTILE
#define FSTAGE (2 * FTILE)
#define FSMEM ((FTILE + 2 * FSTAGE) * 2)      // 46080 bytes
#define LDQ 1536

__global__ void __launch_bounds__(128, 4) flash_hmma(
    const __half* __restrict__ QKV, float* __restrict__ O)
{
    extern __shared__ __half fsm[];
    const uint32_t smb = smem_u32(fsm);
    const int tid = threadIdx.x, wid = tid >> 5, lane = tid & 31;
    const int qt = blockIdx.x, h = blockIdx.y, b = blockIdx.z;
    const int qrow0 = b * SEQ + qt * 64;
    const int col0 = h * 64;
    const float CEXP = 0.044194173824159216f * 1.4426950408889634f;
    const float FOFF = 4.0f * 1.4426950408889634f;

    // Load Q tile [64 x 64]
#pragma unroll
    for (int i = 0; i < 4; i++) {
        int idx = tid + i * 128;
        int r = idx >> 3, ch = idx & 7;
        uint4 v = *reinterpret_cast<const uint4*>(QKV + (size_t)(qrow0 + r) * LDQ + col0 + ch * 8);
        *reinterpret_cast<uint4*>(fsm + r * FPITCH + ch * 8) = v;
    }
    __syncthreads();

    const int warpm = wid * 16;
    const int arow = lane & 15, acol8 = (lane >> 4) * 8;
    uint32_t qf[4][4];
#pragma unroll
    for (int kk = 0; kk < 4; kk++) {
        uint32_t off = (uint32_t)((warpm + arow) * FPITCH + kk * 16 + acol8) * 2;
        ldsm_x4(qf[kk], smb + off);
    }

    auto load_kv = [&](int it, int s) {
        const __half* base = QKV + (size_t)(b * SEQ + it * 64) * LDQ + col0;
        const uint32_t stg = (uint32_t)(FKV0 + s * FSTAGE);
#pragma unroll
        for (int i = 0; i < 8; i++) {
            int idx = tid + i * 128;
            int t = idx >> 9, r = (idx >> 3) & 63, ch = idx & 7;
            uint32_t dst = smb + (stg + (uint32_t)(t * FTILE + r * FPITCH + ch * 8)) * 2;
            cp16(dst, base + (size_t)r * LDQ + (t ? 1024 : 512) + ch * 8);
        }
        cp_commit();
    };

    float lacc[4] = {0.f, 0.f, 0.f, 0.f};
    float o[8][4];
#pragma unroll
    for (int nt = 0; nt < 8; nt++)
#pragma unroll
        for (int j = 0; j < 4; j++) o[nt][j] = 0.f;

    const uint32_t ones2[2] = {0x3C003C00u, 0x3C003C00u};

    const int brow = (lane & 7) + ((lane >> 4) & 1) * 8;
    const int bcol8 = ((lane >> 3) & 1) * 8;
    const int vrow = (lane & 7) + ((lane >> 3) & 1) * 8;
    const int vcol8 = ((lane >> 4) & 1) * 8;

    load_kv(0, 0);

    for (int it = 0; it < SEQ / 64; it++) {
        const int s = it & 1;
        if (it + 1 < SEQ / 64) {
            load_kv(it + 1, s ^ 1);
            asm volatile("cp.async.wait_group 1;" ::: "memory");
        } else {
            asm volatile("cp.async.wait_group 0;" ::: "memory");
        }
        __syncthreads();

        const uint32_t stg = smb + (uint32_t)(FKV0 + s * FSTAGE) * 2;
        const uint32_t kb = stg, vb = stg + FTILE * 2;

        float sacc[8][4];
#pragma unroll
        for (int nt = 0; nt < 8; nt++)
#pragma unroll
            for (int j = 0; j < 4; j++) sacc[nt][j] = 0.f;

#pragma unroll
        for (int kk = 0; kk < 4; kk++) {
#pragma unroll
            for (int np = 0; np < 4; np++) {
                uint32_t bh[4];
                uint32_t off = (uint32_t)((np * 16 + brow) * FPITCH + kk * 16 + bcol8) * 2;
                ldsm_x4(bh, kb + off);
                mma16816(sacc[2 * np],     qf[kk], bh);
                mma16816(sacc[2 * np + 1], qf[kk], bh + 2);
            }
        }

        uint32_t pf[4][4];
#pragma unroll
        for (int np = 0; np < 4; np++) {
#pragma unroll
            for (int half = 0; half < 2; half++) {
                const int nt = 2 * np + half;
                __half2 x01 = __floats2half2_rn(fmaf(sacc[nt][0], CEXP, -FOFF),
                                                fmaf(sacc[nt][1], CEXP, -FOFF));
                __half2 x23 = __floats2half2_rn(fmaf(sacc[nt][2], CEXP, -FOFF),
                                                fmaf(sacc[nt][3], CEXP, -FOFF));
                pf[np][half * 2 + 0] = ex2_h2(*reinterpret_cast<uint32_t*>(&x01));
                pf[np][half * 2 + 1] = ex2_h2(*reinterpret_cast<uint32_t*>(&x23));
            }
        }

#pragma unroll
        for (int kk = 0; kk < 4; kk++) {
            mma16816(lacc, pf[kk], ones2);
#pragma unroll
            for (int dp = 0; dp < 4; dp++) {
                uint32_t vh[4];
                uint32_t off = (uint32_t)((kk * 16 + vrow) * FPITCH + dp * 16 + vcol8) * 2;
                ldsm_x4_t(vh, vb + off);
                mma16816(o[2 * dp],     pf[kk], vh);
                mma16816(o[2 * dp + 1], pf[kk], vh + 2);
            }
        }
        __syncthreads();
    }

    const float inv0 = 1.f / lacc[0], inv1 = 1.f / lacc[2];
    const int r0 = qrow0 + warpm + (lane >> 2), r1 = r0 + 8;
#pragma unroll
    for (int nt = 0; nt < 8; nt++) {
        const int c = col0 + nt * 8 + (lane & 3) * 2;
        *reinterpret_cast<float2*>(O + (size_t)r0 * EMB + c) = make_float2(o[nt][0] * inv0, o[nt][1] * inv0);
        *reinterpret_cast<float2*>(O + (size_t)r1 * EMB + c) = make_float2(o[nt][2] * inv1, o[nt][3] * inv1);
    }
}

// ---------------------------------------------------------------------------
// Fused residual + LayerNorm: 2 rows per 256-thread block (same 4-warp
// per-row reduction order -> bit-identical results), float4-vectorized.
// ---------------------------------------------------------------------------
__global__ void ln_kernel(const float* __restrict__ A,
                          const float* __restrict__ BresF,
                          const __half* __restrict__ BresH, int bres_ld,
                          const float* __restrict__ g, const float* __restrict__ beta,
                          float* __restrict__ out, __half* __restrict__ oh)
{
    const int grp = threadIdx.x >> 7;            // 0 or 1
    const int row = blockIdx.x * 2 + grp;
    const int t = threadIdx.x & 127;             // lane within row-group
    const size_t base = (size_t)row * 128 + t;
    float4 a = reinterpret_cast<const float4*>(A)[base];
    float4 bq;
    if (BresF) {
        bq = reinterpret_cast<const float4*>(BresF)[base];
    } else {
        uint2 raw = *reinterpret_cast<const uint2*>(BresH + (size_t)row * bres_ld + t * 4);
        float2 f0 = __half22float2(*reinterpret_cast<__half2*>(&raw.x));
        float2 f1 = __half22float2(*reinterpret_cast<__half2*>(&raw.y));
        bq = make_float4(f0.x, f0.y, f1.x, f1.y);
    }
    float4 v = make_float4(a.x + bq.x, a.y + bq.y, a.z + bq.z, a.w + bq.w);

    __shared__ float rsum[8], rsq[8];
    float s1 = v.x + v.y + v.z + v.w;
    float s2 = v.x * v.x + v.y * v.y + v.z * v.z + v.w * v.w;
#pragma unroll
    for (int off = 16; off; off >>= 1) {
        s1 += __shfl_xor_sync(0xffffffffu, s1, off);
        s2 += __shfl_xor_sync(0xffffffffu, s2, off);
    }
    const int w = threadIdx.x >> 5;              // 0..7
    if ((threadIdx.x & 31) == 0) { rsum[w] = s1; rsq[w] = s2; }
    __syncthreads();
    const int w0 = grp * 4;
    s1 = rsum[w0] + rsum[w0 + 1] + rsum[w0 + 2] + rsum[w0 + 3];
    s2 = rsq[w0] + rsq[w0 + 1] + rsq[w0 + 2] + rsq[w0 + 3];
    float mu = s1 * (1.f / EMB);
    float var = s2 * (1.f / EMB) - mu * mu;
    float inv = rsqrtf(var + 1e-5f);

    float4 gg = reinterpret_cast<const float4*>(g)[t];
    float4 bb = reinterpret_cast<const float4*>(beta)[t];
    float4 y = make_float4((v.x - mu) * inv * gg.x + bb.x,
                           (v.y - mu) * inv * gg.y + bb.y,
                           (v.z - mu) * inv * gg.z + bb.z,
                           (v.w - mu) * inv * gg.w + bb.w);
    reinterpret_cast<float4*>(out)[base] = y;
    if (oh) {
        __half2 h0 = __floats2half2_rn(y.x, y.y);
        __half2 h1 = __floats2half2_rn(y.z, y.w);
        uint2 pk = make_uint2(*reinterpret_cast<uint32_t*>(&h0), *reinterpret_cast<uint32_t*>(&h1));
        reinterpret_cast<uint2*>(oh)[base] = pk;
    }
}

// ---------------------------------------------------------------------------
// Launch
// ---------------------------------------------------------------------------
extern "C" void kernel_launch(void* const* d_in, const int* in_sizes, int n_in,
                              void* d_out, int out_size)
{
    (void)in_sizes; (void)n_in; (void)out_size;

    const float* x_in = (const float*)d_in[0];
    const float* qW1 = (const float*)d_in[1];  const float* qb1 = (const float*)d_in[2];
    const float* qW2 = (const float*)d_in[3];  const float* qb2 = (const float*)d_in[4];
    const float* kW1 = (const float*)d_in[5];  const float* kb1 = (const float*)d_in[6];
    const float* kW2 = (const float*)d_in[7];  const float* kb2 = (const float*)d_in[8];
    const float* vW1 = (const float*)d_in[9];  const float* vb1 = (const float*)d_in[10];
    const float* vW2 = (const float*)d_in[11]; const float* vb2 = (const float*)d_in[12];
    const float* fW1 = (const float*)d_in[13]; const float* fb1 = (const float*)d_in[14];
    const float* fW2 = (const float*)d_in[15]; const float* fb2 = (const float*)d_in[16];
    const float* ln1g = (const float*)d_in[17]; const float* ln1b = (const float*)d_in[18];
    const float* ln2g = (const float*)d_in[19]; const float* ln2b = (const float*)d_in[20];
    float* out = (float*)d_out;

    float *pctx, *px, *pb1c, *pb2c;
    cudaGetSymbolAddress((void**)&pctx, g_ctx);
    cudaGetSymbolAddress((void**)&px, g_x);
    cudaGetSymbolAddress((void**)&pb1c, g_b1cat);
    cudaGetSymbolAddress((void**)&pb2c, g_b2cat);
    __half *xh, *hidh, *qkvh, *ah, *bh;
    cudaGetSymbolAddress((void**)&xh, g_xh);
    cudaGetSymbolAddress((void**)&hidh, g_hidh);
    cudaGetSymbolAddress((void**)&qkvh, g_qkvh);
    cudaGetSymbolAddress((void**)&ah, g_ah);
    cudaGetSymbolAddress((void**)&bh, g_bh);
    __half *w1h, *w2h, *f1h, *f2h;
    cudaGetSymbolAddress((void**)&w1h, g_w1h);
    cudaGetSymbolAddress((void**)&w2h, g_w2h);
    cudaGetSymbolAddress((void**)&f1h, g_f1h);
    cudaGetSymbolAddress((void**)&f2h, g_f2h);

    cudaFuncSetAttribute(hmma_gemm, cudaFuncAttributeMaxDynamicSharedMemorySize, GSMEM);
    cudaFuncSetAttribute(flash_hmma, cudaFuncAttributeMaxDynamicSharedMemorySize, FSMEM);

    // Prep: coalesced weight transpose + input/bias
    transpose_w<<<2176, 256>>>(qW1, kW1, vW1, qW2, kW2, vW2, fW1, fW2,
                               w1h, w2h, f1h, f2h);
    prep_misc<<<(X_TOTAL + 3072 + 255) / 256, 256>>>(
        x_in, qb1, kb1, vb1, qb2, kb2, vb2, xh, pb1c, pb2c);

    // Merged QKV layer-1
    hmma_gemm<<<dim3(12, 64), 256, GSMEM>>>(xh, 256, 0, w1h, pb1c,
                                            (float*)nullptr, 0, hidh, 1536, 256, 1);
    // Merged QKV layer-2 -> qkv fp16 (q residual read from here later)
    hmma_gemm<<<dim3(12, 64), 256, GSMEM>>>(hidh, 1536, 512, w2h, pb2c,
                                            (float*)nullptr, 0, qkvh, 1536, 512, 0);

    // Attention (round-13 proven config)
    flash_hmma<<<dim3(SEQ / 64, 8, 4), 128, FSMEM>>>(qkvh, pctx);

    // x = LN(ctx + q[fp16 from qkv]), fp16 out for FFN
    ln_kernel<<<TOK / 2, 256>>>(pctx, (float*)nullptr, qkvh, 1536, ln1g, ln1b, px, bh);

    // FFN
    hmma_gemm<<<dim3(8, 64), 256, GSMEM>>>(bh, 512, 0, f1h, fb1,
                                           (float*)nullptr, 0, ah, 1024, 512, 1);
    hmma_gemm<<<dim3(4, 64), 256, GSMEM>>>(ah, 1024, 0, f2h, fb2,
                                           pctx, 512, (__half*)nullptr, 512, 1024, 0);

    // out = LN(x + ff)
    ln_kernel<<<TOK / 2, 256>>>(px, pctx, (const __half*)nullptr, 0, ln2g, ln2b, out, (__half*)nullptr);
}

// round 16
// speedup vs baseline: 1.0828x; 1.0144x over previous
#include <cuda_runtime.h>
#include <cuda_fp16.h>
#include <cstdint>
#include <math.h>

#define TOK 8192
#define EMB 512
#define SEQ 2048

// ---------------------------------------------------------------------------
// Scratch (__device__ globals: no allocs allowed) — all intermediates fp16
// ---------------------------------------------------------------------------
__device__ __half g_xh[TOK * 256];
__device__ __half g_hidh[TOK * 1536];     // QKV layer-1 hidden; reused as FFN out
__device__ __half g_qkvh[TOK * 1536];     // q|k|v concat
__device__ __half g_ctx16[TOK * 512];     // attention out (fp16)
__device__ __half g_ah[TOK * 1024];       // FFN hidden
__device__ __half g_bh[TOK * 512];        // LN1 out (FFN input AND LN2 residual)

// fp16 transposed weights, stored [N][K]; QKV groups contiguous
__device__ __half g_w1h[3][512 * 256];
__device__ __half g_w2h[3][512 * 512];
__device__ __half g_f1h[1024 * 512];
__device__ __half g_f2h[512 * 1024];
__device__ float g_b1cat[1536], g_b2cat[1536];

// ---------------------------------------------------------------------------
// Family-portable PTX helpers
// ---------------------------------------------------------------------------
__device__ __forceinline__ uint32_t smem_u32(const void* p) {
    uint32_t a;
    asm("{ .reg .u64 t; cvta.to.shared.u64 t, %1; cvt.u32.u64 %0, t; }" : "=r"(a) : "l"(p));
    return a;
}
__device__ __forceinline__ void cp16(uint32_t dst, const void* src) {
    asm volatile("cp.async.cg.shared.global [%0], [%1], 16;" :: "r"(dst), "l"(src) : "memory");
}
__device__ __forceinline__ void cp_commit() {
    asm volatile("cp.async.commit_group;" ::: "memory");
}
__device__ __forceinline__ void ldsm_x4(uint32_t* r, uint32_t addr) {
    asm volatile("ldmatrix.sync.aligned.m8n8.x4.shared.b16 {%0,%1,%2,%3}, [%4];"
                 : "=r"(r[0]), "=r"(r[1]), "=r"(r[2]), "=r"(r[3]) : "r"(addr));
}
__device__ __forceinline__ void ldsm_x4_t(uint32_t* r, uint32_t addr) {
    asm volatile("ldmatrix.sync.aligned.m8n8.x4.trans.shared.b16 {%0,%1,%2,%3}, [%4];"
                 : "=r"(r[0]), "=r"(r[1]), "=r"(r[2]), "=r"(r[3]) : "r"(addr));
}
__device__ __forceinline__ void mma16816(float* c, const uint32_t* a, const uint32_t* b) {
    asm volatile("mma.sync.aligned.m16n8k16.row.col.f32.f16.f16.f32 "
                 "{%0,%1,%2,%3}, {%4,%5,%6,%7}, {%8,%9}, {%0,%1,%2,%3};"
                 : "+f"(c[0]), "+f"(c[1]), "+f"(c[2]), "+f"(c[3])
                 : "r"(a[0]), "r"(a[1]), "r"(a[2]), "r"(a[3]), "r"(b[0]), "r"(b[1]));
}
__device__ __forceinline__ uint32_t ex2_h2(uint32_t x) {
    uint32_t r;
    asm("ex2.approx.f16x2 %0, %1;" : "=r"(r) : "r"(x));
    return r;
}

// ---------------------------------------------------------------------------
// Prep A: coalesced 32x32 smem-tile transpose+convert (proven round-15)
// ---------------------------------------------------------------------------
__global__ void __launch_bounds__(256) transpose_w(
    const float* qW1, const float* kW1, const float* vW1,
    const float* qW2, const float* kW2, const float* vW2,
    const float* fW1, const float* fW2,
    __half* w1h, __half* w2h, __half* f1h, __half* f2h)
{
    int bid = blockIdx.x;
    const float* src; __half* dst; int K, N, tk, tn;
    if (bid < 384) {
        int p = bid / 128, r = bid - p * 128;
        src = (p == 0) ? qW1 : (p == 1) ? kW1 : vW1;
        dst = w1h + p * 131072; K = 256; N = 512; tk = r >> 4; tn = r & 15;
    } else if (bid < 1152) {
        int r = bid - 384; int p = r / 256; r -= p * 256;
        src = (p == 0) ? qW2 : (p == 1) ? kW2 : vW2;
        dst = w2h + p * 262144; K = 512; N = 512; tk = r >> 4; tn = r & 15;
    } else if (bid < 1664) {
        int r = bid - 1152;
        src = fW1; dst = f1h; K = 512; N = 1024; tk = r >> 5; tn = r & 31;
    } else {
        int r = bid - 1664;
        src = fW2; dst = f2h; K = 1024; N = 512; tk = r >> 4; tn = r & 15;
    }
    __shared__ __half tile[32][34];
    const int tx = threadIdx.x & 31, ty = threadIdx.x >> 5;
    const int k0 = tk * 32, n0 = tn * 32;
#pragma unroll
    for (int j = 0; j < 4; j++) {
        int k = k0 + ty + j * 8;
        tile[tx][ty + j * 8] = __float2half_rn(src[(size_t)k * N + n0 + tx]);
    }
    __syncthreads();
#pragma unroll
    for (int j = 0; j < 4; j++) {
        int n = n0 + ty + j * 8;
        dst[(size_t)n * K + k0 + tx] = tile[ty + j * 8][tx];
    }
}

// Prep B: input convert + bias concat
#define X_TOTAL (TOK * 256)
__global__ void prep_misc(
    const float* x_in,
    const float* qb1, const float* kb1, const float* vb1,
    const float* qb2, const float* kb2, const float* vb2,
    __half* xh, float* b1cat, float* b2cat)
{
    int idx = blockIdx.x * blockDim.x + threadIdx.x;
    if (idx < X_TOTAL) {
        xh[idx] = __float2half_rn(x_in[idx]);
    } else if (idx < X_TOTAL + 3072) {
        int i = idx - X_TOTAL;
        if (i < 1536) {
            int p = i >> 9, c = i & 511;
            b1cat[i] = (p == 0 ? qb1 : p == 1 ? kb1 : vb1)[c];
        } else {
            int j = i - 1536, p = j >> 9, c = j & 511;
            b2cat[j] = (p == 0 ? qb2 : p == 1 ? kb2 : vb2)[c];
        }
    }
}

// ---------------------------------------------------------------------------
// HMMA fp16 GEMM (proven round-13 config: BK=64, KPAD=72, 3-stage)
// ---------------------------------------------------------------------------
#define KPAD 72
#define TILE_SM (128 * KPAD)
#define STAGE_SM (2 * TILE_SM)
#define GSMEM (3 * STAGE_SM * 2)        // 110592 B

__global__ void __launch_bounds__(256, 2) hmma_gemm(
    const __half* __restrict__ Ah, int lda, int ashift,
    const __half* __restrict__ Bh,
    const float* __restrict__ bias,
    __half* __restrict__ Ch,
    int N, int K, int relu)
{
    extern __shared__ __half sm[];
    const uint32_t smb = smem_u32(sm);
    const int tid = threadIdx.x;
    const int wid = tid >> 5, lane = tid & 31;
    const int bm = blockIdx.y * 128, bn = blockIdx.x * 128;
    const int wm = (wid >> 2) * 64, wn = (wid & 3) * 32;
    const int aoff = (bn >> 9) * ashift;

    float acc[4][4][4];
#pragma unroll
    for (int mt = 0; mt < 4; mt++)
#pragma unroll
        for (int nt = 0; nt < 4; nt++)
#pragma unroll
            for (int r = 0; r < 4; r++) acc[mt][nt][r] = 0.f;

    const int nch = K >> 6;

    auto issue_loads = [&](int ck, int s) {
        const int koff = ck * 64;
        const __half* a_ = Ah + (size_t)bm * lda + aoff + koff;
        const __half* b_ = Bh + (size_t)bn * K + koff;
#pragma unroll
        for (int i = 0; i < 4; i++) {
            int idx = tid + i * 256;
            int r = idx >> 3, c16 = idx & 7;
            uint32_t d0 = smb + (uint32_t)(s * STAGE_SM + r * KPAD + c16 * 8) * 2;
            cp16(d0,               a_ + (size_t)r * lda + c16 * 8);
            cp16(d0 + TILE_SM * 2, b_ + (size_t)r * K + c16 * 8);
        }
        cp_commit();
    };

    issue_loads(0, 0);
    if (nch > 1) issue_loads(1, 1);

    const int arow = (lane & 15);
    const int acol8 = (lane >> 4) * 8;
    const int brow = ((lane >> 4) & 1) * 8 + (lane & 7);
    const int bcol8 = ((lane >> 3) & 1) * 8;

    int s = 0;
    for (int ck = 0; ck < nch; ck++) {
        if (ck < nch - 1) {
            asm volatile("cp.async.wait_group 1;" ::: "memory");
        } else {
            asm volatile("cp.async.wait_group 0;" ::: "memory");
        }
        __syncthreads();
        if (ck + 2 < nch) {
            int s2 = s + 2; if (s2 >= 3) s2 -= 3;
            issue_loads(ck + 2, s2);
        }

        const uint32_t aA = smb + (uint32_t)(s * STAGE_SM) * 2;
        const uint32_t bB = aA + (uint32_t)TILE_SM * 2;

#pragma unroll
        for (int k16 = 0; k16 < 4; k16++) {
            uint32_t fa[4][4], fb[2][4];
#pragma unroll
            for (int mt = 0; mt < 4; mt++) {
                uint32_t off = (uint32_t)((wm + mt * 16 + arow) * KPAD + k16 * 16 + acol8) * 2;
                ldsm_x4(fa[mt], aA + off);
            }
#pragma unroll
            for (int p = 0; p < 2; p++) {
                uint32_t off = (uint32_t)((wn + p * 16 + brow) * KPAD + k16 * 16 + bcol8) * 2;
                ldsm_x4(fb[p], bB + off);
            }
#pragma unroll
            for (int mt = 0; mt < 4; mt++) {
#pragma unroll
                for (int nt = 0; nt < 4; nt++) {
                    mma16816(acc[mt][nt], fa[mt], &fb[nt >> 1][(nt & 1) * 2]);
                }
            }
        }
        if (++s == 3) s = 0;
    }

    const int gid = lane >> 2, tig = lane & 3;
#pragma unroll
    for (int mt = 0; mt < 4; mt++) {
#pragma unroll
        for (int nt = 0; nt < 4; nt++) {
            const int c0 = bn + wn + nt * 8 + tig * 2;
            const float bb0 = __ldg(&bias[c0]), bb1 = __ldg(&bias[c0 + 1]);
#pragma unroll
            for (int half = 0; half < 2; half++) {
                const int r = bm + wm + mt * 16 + gid + half * 8;
                float v0 = acc[mt][nt][half * 2 + 0] + bb0;
                float v1 = acc[mt][nt][half * 2 + 1] + bb1;
                if (relu) { v0 = fmaxf(v0, 0.f); v1 = fmaxf(v1, 0.f); }
                __half2 hh = __floats2half2_rn(v0, v1);
                *reinterpret_cast<__half2*>(Ch + (size_t)r * N + c0) = hh;
            }
        }
    }
}

// ---------------------------------------------------------------------------
// HMMA flash attention — round-11/13 v5 structure; epilogue writes fp16
// ---------------------------------------------------------------------------
#define FPITCH 72
#define FTILE (64 * FPITCH)
#define FKV0 FTILE
#define FSTAGE (2 * FTILE)
#define FSMEM ((FTILE + 2 * FSTAGE) * 2)      // 46080 bytes
#define LDQ 1536

__global__ void __launch_bounds__(128, 4) flash_hmma(
    const __half* __restrict__ QKV, __half* __restrict__ O)
{
    extern __shared__ __half fsm[];
    const uint32_t smb = smem_u32(fsm);
    const int tid = threadIdx.x, wid = tid >> 5, lane = tid & 31;
    const int qt = blockIdx.x, h = blockIdx.y, b = blockIdx.z;
    const int qrow0 = b * SEQ + qt * 64;
    const int col0 = h * 64;
    const float CEXP = 0.044194173824159216f * 1.4426950408889634f;
    const float FOFF = 4.0f * 1.4426950408889634f;

#pragma unroll
    for (int i = 0; i < 4; i++) {
        int idx = tid + i * 128;
        int r = idx >> 3, ch = idx & 7;
        uint4 v = *reinterpret_cast<const uint4*>(QKV + (size_t)(qrow0 + r) * LDQ + col0 + ch * 8);
        *reinterpret_cast<uint4*>(fsm + r * FPITCH + ch * 8) = v;
    }
    __syncthreads();

    const int warpm = wid * 16;
    const int arow = lane & 15, acol8 = (lane >> 4) * 8;
    uint32_t qf[4][4];
#pragma unroll
    for (int kk = 0; kk < 4; kk++) {
        uint32_t off = (uint32_t)((warpm + arow) * FPITCH + kk * 16 + acol8) * 2;
        ldsm_x4(qf[kk], smb + off);
    }

    auto load_kv = [&](int it, int s) {
        const __half* base = QKV + (size_t)(b * SEQ + it * 64) * LDQ + col0;
        const uint32_t stg = (uint32_t)(FKV0 + s * FSTAGE);
#pragma unroll
        for (int i = 0; i < 8; i++) {
            int idx = tid + i * 128;
            int t = idx >> 9, r = (idx >> 3) & 63, ch = idx & 7;
            uint32_t dst = smb + (stg + (uint32_t)(t * FTILE + r * FPITCH + ch * 8)) * 2;
            cp16(dst, base + (size_t)r * LDQ + (t ? 1024 : 512) + ch * 8);
        }
        cp_commit();
    };

    float lacc[4] = {0.f, 0.f, 0.f, 0.f};
    float o[8][4];
#pragma unroll
    for (int nt = 0; nt < 8; nt++)
#pragma unroll
        for (int j = 0; j < 4; j++) o[nt][j] = 0.f;

    const uint32_t ones2[2] = {0x3C003C00u, 0x3C003C00u};

    const int brow = (lane & 7) + ((lane >> 4) & 1) * 8;
    const int bcol8 = ((lane >> 3) & 1) * 8;
    const int vrow = (lane & 7) + ((lane >> 3) & 1) * 8;
    const int vcol8 = ((lane >> 4) & 1) * 8;

    load_kv(0, 0);

    for (int it = 0; it < SEQ / 64; it++) {
        const int s = it & 1;
        if (it + 1 < SEQ / 64) {
            load_kv(it + 1, s ^ 1);
            asm volatile("cp.async.wait_group 1;" ::: "memory");
        } else {
            asm volatile("cp.async.wait_group 0;" ::: "memory");
        }
        __syncthreads();

        const uint32_t stg = smb + (uint32_t)(FKV0 + s * FSTAGE) * 2;
        const uint32_t kb = stg, vb = stg + FTILE * 2;

        float sacc[8][4];
#pragma unroll
        for (int nt = 0; nt < 8; nt++)
#pragma unroll
            for (int j = 0; j < 4; j++) sacc[nt][j] = 0.f;

#pragma unroll
        for (int kk = 0; kk < 4; kk++) {
#pragma unroll
            for (int np = 0; np < 4; np++) {
                uint32_t bh[4];
                uint32_t off = (uint32_t)((np * 16 + brow) * FPITCH + kk * 16 + bcol8) * 2;
                ldsm_x4(bh, kb + off);
                mma16816(sacc[2 * np],     qf[kk], bh);
                mma16816(sacc[2 * np + 1], qf[kk], bh + 2);
            }
        }

        uint32_t pf[4][4];
#pragma unroll
        for (int np = 0; np < 4; np++) {
#pragma unroll
            for (int half = 0; half < 2; half++) {
                const int nt = 2 * np + half;
                __half2 x01 = __floats2half2_rn(fmaf(sacc[nt][0], CEXP, -FOFF),
                                                fmaf(sacc[nt][1], CEXP, -FOFF));
                __half2 x23 = __floats2half2_rn(fmaf(sacc[nt][2], CEXP, -FOFF),
                                                fmaf(sacc[nt][3], CEXP, -FOFF));
                pf[np][half * 2 + 0] = ex2_h2(*reinterpret_cast<uint32_t*>(&x01));
                pf[np][half * 2 + 1] = ex2_h2(*reinterpret_cast<uint32_t*>(&x23));
            }
        }

#pragma unroll
        for (int kk = 0; kk < 4; kk++) {
            mma16816(lacc, pf[kk], ones2);
#pragma unroll
            for (int dp = 0; dp < 4; dp++) {
                uint32_t vh[4];
                uint32_t off = (uint32_t)((kk * 16 + vrow) * FPITCH + dp * 16 + vcol8) * 2;
                ldsm_x4_t(vh, vb + off);
                mma16816(o[2 * dp],     pf[kk], vh);
                mma16816(o[2 * dp + 1], pf[kk], vh + 2);
            }
        }
        __syncthreads();
    }

    const float inv0 = 1.f / lacc[0], inv1 = 1.f / lacc[2];
    const int r0 = qrow0 + warpm + (lane >> 2), r1 = r0 + 8;
#pragma unroll
    for (int nt = 0; nt < 8; nt++) {
        const int c = col0 + nt * 8 + (lane & 3) * 2;
        __half2 h0 = __floats2half2_rn(o[nt][0] * inv0, o[nt][1] * inv0);
        __half2 h1 = __floats2half2_rn(o[nt][2] * inv1, o[nt][3] * inv1);
        *reinterpret_cast<__half2*>(O + (size_t)r0 * EMB + c) = h0;
        *reinterpret_cast<__half2*>(O + (size_t)r1 * EMB + c) = h1;
    }
}

// ---------------------------------------------------------------------------
// Fused residual + LayerNorm, all-fp16 I/O: y = LN(A + B). 2 rows per block.
// Optional fp16 output (oh) and/or fp32 output (of).
// ---------------------------------------------------------------------------
__global__ void ln16(const __half* __restrict__ A, int lda,
                     const __half* __restrict__ B, int ldb,
                     const float* __restrict__ g, const float* __restrict__ beta,
                     __half* __restrict__ oh, float* __restrict__ of)
{
    const int grp = threadIdx.x >> 7;
    const int row = blockIdx.x * 2 + grp;
    const int t = threadIdx.x & 127;
    uint2 ra = *reinterpret_cast<const uint2*>(A + (size_t)row * lda + t * 4);
    uint2 rb = *reinterpret_cast<const uint2*>(B + (size_t)row * ldb + t * 4);
    float2 a0 = __half22float2(*reinterpret_cast<__half2*>(&ra.x));
    float2 a1 = __half22float2(*reinterpret_cast<__half2*>(&ra.y));
    float2 b0 = __half22float2(*reinterpret_cast<__half2*>(&rb.x));
    float2 b1 = __half22float2(*reinterpret_cast<__half2*>(&rb.y));
    float4 v = make_float4(a0.x + b0.x, a0.y + b0.y, a1.x + b1.x, a1.y + b1.y);

    __shared__ float rsum[8], rsq[8];
    float s1 = v.x + v.y + v.z + v.w;
    float s2 = v.x * v.x + v.y * v.y + v.z * v.z + v.w * v.w;
#pragma unroll
    for (int off = 16; off; off >>= 1) {
        s1 += __shfl_xor_sync(0xffffffffu, s1, off);
        s2 += __shfl_xor_sync(0xffffffffu, s2, off);
    }
    const int w = threadIdx.x >> 5;
    if ((threadIdx.x & 31) == 0) { rsum[w] = s1; rsq[w] = s2; }
    __syncthreads();
    const int w0 = grp * 4;
    s1 = rsum[w0] + rsum[w0 + 1] + rsum[w0 + 2] + rsum[w0 + 3];
    s2 = rsq[w0] + rsq[w0 + 1] + rsq[w0 + 2] + rsq[w0 + 3];
    float mu = s1 * (1.f / EMB);
    float var = s2 * (1.f / EMB) - mu * mu;
    float inv = rsqrtf(var + 1e-5f);

    float4 gg = reinterpret_cast<const float4*>(g)[t];
    float4 bb = reinterpret_cast<const float4*>(beta)[t];
    float4 y = make_float4((v.x - mu) * inv * gg.x + bb.x,
                           (v.y - mu) * inv * gg.y + bb.y,
                           (v.z - mu) * inv * gg.z + bb.z,
                           (v.w - mu) * inv * gg.w + bb.w);
    if (of) reinterpret_cast<float4*>(of)[(size_t)row * 128 + t] = y;
    if (oh) {
        __half2 h0 = __floats2half2_rn(y.x, y.y);
        __half2 h1 = __floats2half2_rn(y.z, y.w);
        uint2 pk = make_uint2(*reinterpret_cast<uint32_t*>(&h0), *reinterpret_cast<uint32_t*>(&h1));
        reinterpret_cast<uint2*>(oh)[(size_t)row * 128 + t] = pk;
    }
}

// ---------------------------------------------------------------------------
// Launch
// ---------------------------------------------------------------------------
extern "C" void kernel_launch(void* const* d_in, const int* in_sizes, int n_in,
                              void* d_out, int out_size)
{
    (void)in_sizes; (void)n_in; (void)out_size;

    const float* x_in = (const float*)d_in[0];
    const float* qW1 = (const float*)d_in[1];  const float* qb1 = (const float*)d_in[2];
    const float* qW2 = (const float*)d_in[3];  const float* qb2 = (const float*)d_in[4];
    const float* kW1 = (const float*)d_in[5];  const float* kb1 = (const float*)d_in[6];
    const float* kW2 = (const float*)d_in[7];  const float* kb2 = (const float*)d_in[8];
    const float* vW1 = (const float*)d_in[9];  const float* vb1 = (const float*)d_in[10];
    const float* vW2 = (const float*)d_in[11]; const float* vb2 = (const float*)d_in[12];
    const float* fW1 = (const float*)d_in[13]; const float* fb1 = (const float*)d_in[14];
    const float* fW2 = (const float*)d_in[15]; const float* fb2 = (const float*)d_in[16];
    const float* ln1g = (const float*)d_in[17]; const float* ln1b = (const float*)d_in[18];
    const float* ln2g = (const float*)d_in[19]; const float* ln2b = (const float*)d_in[20];
    float* out = (float*)d_out;

    float *pb1c, *pb2c;
    cudaGetSymbolAddress((void**)&pb1c, g_b1cat);
    cudaGetSymbolAddress((void**)&pb2c, g_b2cat);
    __half *xh, *hidh, *qkvh, *ctx16, *ah, *bh;
    cudaGetSymbolAddress((void**)&xh, g_xh);
    cudaGetSymbolAddress((void**)&hidh, g_hidh);
    cudaGetSymbolAddress((void**)&qkvh, g_qkvh);
    cudaGetSymbolAddress((void**)&ctx16, g_ctx16);
    cudaGetSymbolAddress((void**)&ah, g_ah);
    cudaGetSymbolAddress((void**)&bh, g_bh);
    __half *w1h, *w2h, *f1h, *f2h;
    cudaGetSymbolAddress((void**)&w1h, g_w1h);
    cudaGetSymbolAddress((void**)&w2h, g_w2h);
    cudaGetSymbolAddress((void**)&f1h, g_f1h);
    cudaGetSymbolAddress((void**)&f2h, g_f2h);

    __half* ff16 = hidh;   // hidh is free after QKV layer-2 consumes it

    cudaFuncSetAttribute(hmma_gemm, cudaFuncAttributeMaxDynamicSharedMemorySize, GSMEM);
    cudaFuncSetAttribute(flash_hmma, cudaFuncAttributeMaxDynamicSharedMemorySize, FSMEM);

    // Prep
    transpose_w<<<2176, 256>>>(qW1, kW1, vW1, qW2, kW2, vW2, fW1, fW2,
                               w1h, w2h, f1h, f2h);
    prep_misc<<<(X_TOTAL + 3072 + 255) / 256, 256>>>(
        x_in, qb1, kb1, vb1, qb2, kb2, vb2, xh, pb1c, pb2c);

    // Merged QKV layer-1
    hmma_gemm<<<dim3(12, 64), 256, GSMEM>>>(xh, 256, 0, w1h, pb1c, hidh, 1536, 256, 1);
    // Merged QKV layer-2 -> qkv fp16
    hmma_gemm<<<dim3(12, 64), 256, GSMEM>>>(hidh, 1536, 512, w2h, pb2c, qkvh, 1536, 512, 0);

    // Attention -> ctx16 (fp16)
    flash_hmma<<<dim3(SEQ / 64, 8, 4), 128, FSMEM>>>(qkvh, ctx16);

    // x = LN(ctx + q) -> bh (fp16; serves as FFN input AND LN2 residual)
    ln16<<<TOK / 2, 256>>>(ctx16, 512, qkvh, 1536, ln1g, ln1b, bh, (float*)nullptr);

    // FFN (ff16 reuses hidh)
    hmma_gemm<<<dim3(8, 64), 256, GSMEM>>>(bh, 512, 0, f1h, fb1, ah, 1024, 512, 1);
    hmma_gemm<<<dim3(4, 64), 256, GSMEM>>>(ah, 1024, 0, f2h, fb2, ff16, 512, 1024, 0);

    // out = LN(ff + x) -> fp32 output
    ln16<<<TOK / 2, 256>>>(ff16, 512, bh, 512, ln2g, ln2b, (__half*)nullptr, out);
}

// round 17
// speedup vs baseline: 1.1463x; 1.0587x over previous
#include <cuda_runtime.h>
#include <cuda_fp16.h>
#include <cstdint>
#include <math.h>

#define TOK 8192
#define EMB 512
#define SEQ 2048

// ---------------------------------------------------------------------------
// Scratch (__device__ globals: no allocs allowed) — all intermediates fp16
// ---------------------------------------------------------------------------
__device__ __half g_xh[TOK * 256];
__device__ __half g_hidh[TOK * 1536];     // QKV layer-1 hidden; reused as FFN out
__device__ __half g_qkvh[TOK * 1536];     // q|k|v concat
__device__ __half g_ctx16[TOK * 512];     // attention out (fp16)
__device__ __half g_ah[TOK * 1024];       // FFN hidden
__device__ __half g_bh[TOK * 512];        // LN1 out (FFN input AND LN2 residual)

// fp16 transposed weights, stored [N][K]; QKV groups contiguous
__device__ __half g_w1h[3][512 * 256];
__device__ __half g_w2h[3][512 * 512];
__device__ __half g_f1h[1024 * 512];
__device__ __half g_f2h[512 * 1024];
__device__ float g_b1cat[1536], g_b2cat[1536];

// ---------------------------------------------------------------------------
// Family-portable PTX helpers
// ---------------------------------------------------------------------------
__device__ __forceinline__ uint32_t smem_u32(const void* p) {
    uint32_t a;
    asm("{ .reg .u64 t; cvta.to.shared.u64 t, %1; cvt.u32.u64 %0, t; }" : "=r"(a) : "l"(p));
    return a;
}
__device__ __forceinline__ void cp16(uint32_t dst, const void* src) {
    asm volatile("cp.async.cg.shared.global [%0], [%1], 16;" :: "r"(dst), "l"(src) : "memory");
}
__device__ __forceinline__ void cp_commit() {
    asm volatile("cp.async.commit_group;" ::: "memory");
}
__device__ __forceinline__ void ldsm_x4(uint32_t* r, uint32_t addr) {
    asm volatile("ldmatrix.sync.aligned.m8n8.x4.shared.b16 {%0,%1,%2,%3}, [%4];"
                 : "=r"(r[0]), "=r"(r[1]), "=r"(r[2]), "=r"(r[3]) : "r"(addr));
}
__device__ __forceinline__ void ldsm_x4_t(uint32_t* r, uint32_t addr) {
    asm volatile("ldmatrix.sync.aligned.m8n8.x4.trans.shared.b16 {%0,%1,%2,%3}, [%4];"
                 : "=r"(r[0]), "=r"(r[1]), "=r"(r[2]), "=r"(r[3]) : "r"(addr));
}
__device__ __forceinline__ void mma16816(float* c, const uint32_t* a, const uint32_t* b) {
    asm volatile("mma.sync.aligned.m16n8k16.row.col.f32.f16.f16.f32 "
                 "{%0,%1,%2,%3}, {%4,%5,%6,%7}, {%8,%9}, {%0,%1,%2,%3};"
                 : "+f"(c[0]), "+f"(c[1]), "+f"(c[2]), "+f"(c[3])
                 : "r"(a[0]), "r"(a[1]), "r"(a[2]), "r"(a[3]), "r"(b[0]), "r"(b[1]));
}
__device__ __forceinline__ uint32_t ex2_h2(uint32_t x) {
    uint32_t r;
    asm("ex2.approx.f16x2 %0, %1;" : "=r"(r) : "r"(x));
    return r;
}

// ---------------------------------------------------------------------------
// Single prep kernel: weight transpose tiles + input convert + bias concat.
// Blocks 0..2175: 32x32 transpose tiles; 2176..: x convert + biases.
// ---------------------------------------------------------------------------
#define X_TOTAL (TOK * 256)
#define XB ((X_TOTAL + 3072 + 255) / 256)

__global__ void __launch_bounds__(256) prep_all(
    const float* x_in,
    const float* qW1, const float* kW1, const float* vW1,
    const float* qW2, const float* kW2, const float* vW2,
    const float* fW1, const float* fW2,
    const float* qb1, const float* kb1, const float* vb1,
    const float* qb2, const float* kb2, const float* vb2,
    __half* w1h, __half* w2h, __half* f1h, __half* f2h,
    __half* xh, float* b1cat, float* b2cat)
{
    int bid = blockIdx.x;
    if (bid >= 2176) {                    // x convert + bias concat
        int idx = (bid - 2176) * 256 + threadIdx.x;
        if (idx < X_TOTAL) {
            xh[idx] = __float2half_rn(x_in[idx]);
        } else if (idx < X_TOTAL + 3072) {
            int i = idx - X_TOTAL;
            if (i < 1536) {
                int p = i >> 9, c = i & 511;
                b1cat[i] = (p == 0 ? qb1 : p == 1 ? kb1 : vb1)[c];
            } else {
                int j = i - 1536, p = j >> 9, c = j & 511;
                b2cat[j] = (p == 0 ? qb2 : p == 1 ? kb2 : vb2)[c];
            }
        }
        return;
    }
    const float* src; __half* dst; int K, N, tk, tn;
    if (bid < 384) {
        int p = bid / 128, r = bid - p * 128;
        src = (p == 0) ? qW1 : (p == 1) ? kW1 : vW1;
        dst = w1h + p * 131072; K = 256; N = 512; tk = r >> 4; tn = r & 15;
    } else if (bid < 1152) {
        int r = bid - 384; int p = r / 256; r -= p * 256;
        src = (p == 0) ? qW2 : (p == 1) ? kW2 : vW2;
        dst = w2h + p * 262144; K = 512; N = 512; tk = r >> 4; tn = r & 15;
    } else if (bid < 1664) {
        int r = bid - 1152;
        src = fW1; dst = f1h; K = 512; N = 1024; tk = r >> 5; tn = r & 31;
    } else {
        int r = bid - 1664;
        src = fW2; dst = f2h; K = 1024; N = 512; tk = r >> 4; tn = r & 15;
    }
    __shared__ __half tile[32][34];
    const int tx = threadIdx.x & 31, ty = threadIdx.x >> 5;
    const int k0 = tk * 32, n0 = tn * 32;
#pragma unroll
    for (int j = 0; j < 4; j++) {
        int k = k0 + ty + j * 8;
        tile[tx][ty + j * 8] = __float2half_rn(src[(size_t)k * N + n0 + tx]);
    }
    __syncthreads();
#pragma unroll
    for (int j = 0; j < 4; j++) {
        int n = n0 + ty + j * 8;
        dst[(size_t)n * K + k0 + tx] = tile[ty + j * 8][tx];
    }
}

// ---------------------------------------------------------------------------
// HMMA fp16 GEMM: BK=64, KPAD=72, 3-stage; cp.async issue interleaved
// into the k16 loop (2 per thread per k16) to smooth LSU pressure.
// ---------------------------------------------------------------------------
#define KPAD 72
#define TILE_SM (128 * KPAD)
#define STAGE_SM (2 * TILE_SM)
#define GSMEM (3 * STAGE_SM * 2)        // 110592 B

__global__ void __launch_bounds__(256, 2) hmma_gemm(
    const __half* __restrict__ Ah, int lda, int ashift,
    const __half* __restrict__ Bh,
    const float* __restrict__ bias,
    __half* __restrict__ Ch,
    int N, int K, int relu)
{
    extern __shared__ __half sm[];
    const uint32_t smb = smem_u32(sm);
    const int tid = threadIdx.x;
    const int wid = tid >> 5, lane = tid & 31;
    const int bm = blockIdx.y * 128, bn = blockIdx.x * 128;
    const int wm = (wid >> 2) * 64, wn = (wid & 3) * 32;
    const int aoff = (bn >> 9) * ashift;

    float acc[4][4][4];
#pragma unroll
    for (int mt = 0; mt < 4; mt++)
#pragma unroll
        for (int nt = 0; nt < 4; nt++)
#pragma unroll
            for (int r = 0; r < 4; r++) acc[mt][nt][r] = 0.f;

    const int nch = K >> 6;

    // one 16B chunk-pair of the stage load (i = 0..3)
    auto issue_part = [&](int ck, int s, int i) {
        const int koff = ck * 64;
        int idx = tid + i * 256;
        int r = idx >> 3, c16 = idx & 7;
        uint32_t d0 = smb + (uint32_t)(s * STAGE_SM + r * KPAD + c16 * 8) * 2;
        cp16(d0,               Ah + (size_t)bm * lda + aoff + koff + (size_t)r * lda + c16 * 8);
        cp16(d0 + TILE_SM * 2, Bh + (size_t)bn * K + koff + (size_t)r * K + c16 * 8);
    };
    auto issue_full = [&](int ck, int s) {
#pragma unroll
        for (int i = 0; i < 4; i++) issue_part(ck, s, i);
        cp_commit();
    };

    issue_full(0, 0);
    if (nch > 1) issue_full(1, 1);

    const int arow = (lane & 15);
    const int acol8 = (lane >> 4) * 8;
    const int brow = ((lane >> 4) & 1) * 8 + (lane & 7);
    const int bcol8 = ((lane >> 3) & 1) * 8;

    int s = 0;
    for (int ck = 0; ck < nch; ck++) {
        if (ck < nch - 1) {
            asm volatile("cp.async.wait_group 1;" ::: "memory");
        } else {
            asm volatile("cp.async.wait_group 0;" ::: "memory");
        }
        __syncthreads();
        const bool pre = (ck + 2 < nch);
        int s2 = s + 2; if (s2 >= 3) s2 -= 3;

        const uint32_t aA = smb + (uint32_t)(s * STAGE_SM) * 2;
        const uint32_t bB = aA + (uint32_t)TILE_SM * 2;

#pragma unroll
        for (int k16 = 0; k16 < 4; k16++) {
            if (pre) issue_part(ck + 2, s2, k16);   // interleaved LDGSTS
            uint32_t fa[4][4], fb[2][4];
#pragma unroll
            for (int mt = 0; mt < 4; mt++) {
                uint32_t off = (uint32_t)((wm + mt * 16 + arow) * KPAD + k16 * 16 + acol8) * 2;
                ldsm_x4(fa[mt], aA + off);
            }
#pragma unroll
            for (int p = 0; p < 2; p++) {
                uint32_t off = (uint32_t)((wn + p * 16 + brow) * KPAD + k16 * 16 + bcol8) * 2;
                ldsm_x4(fb[p], bB + off);
            }
#pragma unroll
            for (int mt = 0; mt < 4; mt++) {
#pragma unroll
                for (int nt = 0; nt < 4; nt++) {
                    mma16816(acc[mt][nt], fa[mt], &fb[nt >> 1][(nt & 1) * 2]);
                }
            }
        }
        if (pre) cp_commit();
        if (++s == 3) s = 0;
    }

    const int gid = lane >> 2, tig = lane & 3;
#pragma unroll
    for (int mt = 0; mt < 4; mt++) {
#pragma unroll
        for (int nt = 0; nt < 4; nt++) {
            const int c0 = bn + wn + nt * 8 + tig * 2;
            const float bb0 = __ldg(&bias[c0]), bb1 = __ldg(&bias[c0 + 1]);
#pragma unroll
            for (int half = 0; half < 2; half++) {
                const int r = bm + wm + mt * 16 + gid + half * 8;
                float v0 = acc[mt][nt][half * 2 + 0] + bb0;
                float v1 = acc[mt][nt][half * 2 + 1] + bb1;
                if (relu) { v0 = fmaxf(v0, 0.f); v1 = fmaxf(v1, 0.f); }
                __half2 hh = __floats2half2_rn(v0, v1);
                *reinterpret_cast<__half2*>(Ch + (size_t)r * N + c0) = hh;
            }
        }
    }
}

// ---------------------------------------------------------------------------
// HMMA flash attention — v5 structure; cp.async interleaved into QK loop
// ---------------------------------------------------------------------------
#define FPITCH 72
#define FTILE (64 * FPITCH)
#define FKV0 FTILE
#define FSTAGE (2 * FTILE)
#define FSMEM ((FTILE + 2 * FSTAGE) * 2)      // 46080 bytes
#define LDQ 1536

__global__ void __launch_bounds__(128, 4) flash_hmma(
    const __half* __restrict__ QKV, __half* __restrict__ O)
{
    extern __shared__ __half fsm[];
    const uint32_t smb = smem_u32(fsm);
    const int tid = threadIdx.x, wid = tid >> 5, lane = tid & 31;
    const int qt = blockIdx.x, h = blockIdx.y, b = blockIdx.z;
    const int qrow0 = b * SEQ + qt * 64;
    const int col0 = h * 64;
    const float CEXP = 0.044194173824159216f * 1.4426950408889634f;
    const float FOFF = 4.0f * 1.4426950408889634f;

#pragma unroll
    for (int i = 0; i < 4; i++) {
        int idx = tid + i * 128;
        int r = idx >> 3, ch = idx & 7;
        uint4 v = *reinterpret_cast<const uint4*>(QKV + (size_t)(qrow0 + r) * LDQ + col0 + ch * 8);
        *reinterpret_cast<uint4*>(fsm + r * FPITCH + ch * 8) = v;
    }
    __syncthreads();

    const int warpm = wid * 16;
    const int arow = lane & 15, acol8 = (lane >> 4) * 8;
    uint32_t qf[4][4];
#pragma unroll
    for (int kk = 0; kk < 4; kk++) {
        uint32_t off = (uint32_t)((warpm + arow) * FPITCH + kk * 16 + acol8) * 2;
        ldsm_x4(qf[kk], smb + off);
    }

    // one 2-cp16 slice of the K/V stage load (i = 0..3)
    auto load_kv_part = [&](int it, int s, int i) {
        const __half* base = QKV + (size_t)(b * SEQ + it * 64) * LDQ + col0;
        const uint32_t stg = (uint32_t)(FKV0 + s * FSTAGE);
#pragma unroll
        for (int j = 0; j < 2; j++) {
            int idx = tid + (i * 2 + j) * 128;
            int t = idx >> 9, r = (idx >> 3) & 63, ch = idx & 7;
            uint32_t dst = smb + (stg + (uint32_t)(t * FTILE + r * FPITCH + ch * 8)) * 2;
            cp16(dst, base + (size_t)r * LDQ + (t ? 1024 : 512) + ch * 8);
        }
    };
    auto load_kv_full = [&](int it, int s) {
#pragma unroll
        for (int i = 0; i < 4; i++) load_kv_part(it, s, i);
        cp_commit();
    };

    float lacc[4] = {0.f, 0.f, 0.f, 0.f};
    float o[8][4];
#pragma unroll
    for (int nt = 0; nt < 8; nt++)
#pragma unroll
        for (int j = 0; j < 4; j++) o[nt][j] = 0.f;

    const uint32_t ones2[2] = {0x3C003C00u, 0x3C003C00u};

    const int brow = (lane & 7) + ((lane >> 4) & 1) * 8;
    const int bcol8 = ((lane >> 3) & 1) * 8;
    const int vrow = (lane & 7) + ((lane >> 3) & 1) * 8;
    const int vcol8 = ((lane >> 4) & 1) * 8;

    load_kv_full(0, 0);

    for (int it = 0; it < SEQ / 64; it++) {
        const int s = it & 1;
        const bool pre = (it + 1 < SEQ / 64);
        if (!pre) {
            asm volatile("cp.async.wait_group 0;" ::: "memory");
        } else if (it > 0) {
            asm volatile("cp.async.wait_group 1;" ::: "memory");
        }
        // it==0 with pre: group 0 already the only one outstanding; wait it
        if (it == 0 && pre) { asm volatile("cp.async.wait_group 0;" ::: "memory"); }
        __syncthreads();

        const uint32_t stg = smb + (uint32_t)(FKV0 + s * FSTAGE) * 2;
        const uint32_t kb = stg, vb = stg + FTILE * 2;

        float sacc[8][4];
#pragma unroll
        for (int nt = 0; nt < 8; nt++)
#pragma unroll
            for (int j = 0; j < 4; j++) sacc[nt][j] = 0.f;

#pragma unroll
        for (int kk = 0; kk < 4; kk++) {
            if (pre) load_kv_part(it + 1, s ^ 1, kk);   // interleaved LDGSTS
#pragma unroll
            for (int np = 0; np < 4; np++) {
                uint32_t bh[4];
                uint32_t off = (uint32_t)((np * 16 + brow) * FPITCH + kk * 16 + bcol8) * 2;
                ldsm_x4(bh, kb + off);
                mma16816(sacc[2 * np],     qf[kk], bh);
                mma16816(sacc[2 * np + 1], qf[kk], bh + 2);
            }
        }
        if (pre) cp_commit();

        uint32_t pf[4][4];
#pragma unroll
        for (int np = 0; np < 4; np++) {
#pragma unroll
            for (int half = 0; half < 2; half++) {
                const int nt = 2 * np + half;
                __half2 x01 = __floats2half2_rn(fmaf(sacc[nt][0], CEXP, -FOFF),
                                                fmaf(sacc[nt][1], CEXP, -FOFF));
                __half2 x23 = __floats2half2_rn(fmaf(sacc[nt][2], CEXP, -FOFF),
                                                fmaf(sacc[nt][3], CEXP, -FOFF));
                pf[np][half * 2 + 0] = ex2_h2(*reinterpret_cast<uint32_t*>(&x01));
                pf[np][half * 2 + 1] = ex2_h2(*reinterpret_cast<uint32_t*>(&x23));
            }
        }

#pragma unroll
        for (int kk = 0; kk < 4; kk++) {
            mma16816(lacc, pf[kk], ones2);
#pragma unroll
            for (int dp = 0; dp < 4; dp++) {
                uint32_t vh[4];
                uint32_t off = (uint32_t)((kk * 16 + vrow) * FPITCH + dp * 16 + vcol8) * 2;
                ldsm_x4_t(vh, vb + off);
                mma16816(o[2 * dp],     pf[kk], vh);
                mma16816(o[2 * dp + 1], pf[kk], vh + 2);
            }
        }
        __syncthreads();
    }

    const float inv0 = 1.f / lacc[0], inv1 = 1.f / lacc[2];
    const int r0 = qrow0 + warpm + (lane >> 2), r1 = r0 + 8;
#pragma unroll
    for (int nt = 0; nt < 8; nt++) {
        const int c = col0 + nt * 8 + (lane & 3) * 2;
        __half2 h0 = __floats2half2_rn(o[nt][0] * inv0, o[nt][1] * inv0);
        __half2 h1 = __floats2half2_rn(o[nt][2] * inv1, o[nt][3] * inv1);
        *reinterpret_cast<__half2*>(O + (size_t)r0 * EMB + c) = h0;
        *reinterpret_cast<__half2*>(O + (size_t)r1 * EMB + c) = h1;
    }
}

// ---------------------------------------------------------------------------
// Fused residual + LayerNorm, all-fp16 I/O (proven round-16)
// ---------------------------------------------------------------------------
__global__ void ln16(const __half* __restrict__ A, int lda,
                     const __half* __restrict__ B, int ldb,
                     const float* __restrict__ g, const float* __restrict__ beta,
                     __half* __restrict__ oh, float* __restrict__ of)
{
    const int grp = threadIdx.x >> 7;
    const int row = blockIdx.x * 2 + grp;
    const int t = threadIdx.x & 127;
    uint2 ra = *reinterpret_cast<const uint2*>(A + (size_t)row * lda + t * 4);
    uint2 rb = *reinterpret_cast<const uint2*>(B + (size_t)row * ldb + t * 4);
    float2 a0 = __half22float2(*reinterpret_cast<__half2*>(&ra.x));
    float2 a1 = __half22float2(*reinterpret_cast<__half2*>(&ra.y));
    float2 b0 = __half22float2(*reinterpret_cast<__half2*>(&rb.x));
    float2 b1 = __half22float2(*reinterpret_cast<__half2*>(&rb.y));
    float4 v = make_float4(a0.x + b0.x, a0.y + b0.y, a1.x + b1.x, a1.y + b1.y);

    __shared__ float rsum[8], rsq[8];
    float s1 = v.x + v.y + v.z + v.w;
    float s2 = v.x * v.x + v.y * v.y + v.z * v.z + v.w * v.w;
#pragma unroll
    for (int off = 16; off; off >>= 1) {
        s1 += __shfl_xor_sync(0xffffffffu, s1, off);
        s2 += __shfl_xor_sync(0xffffffffu, s2, off);
    }
    const int w = threadIdx.x >> 5;
    if ((threadIdx.x & 31) == 0) { rsum[w] = s1; rsq[w] = s2; }
    __syncthreads();
    const int w0 = grp * 4;
    s1 = rsum[w0] + rsum[w0 + 1] + rsum[w0 + 2] + rsum[w0 + 3];
    s2 = rsq[w0] + rsq[w0 + 1] + rsq[w0 + 2] + rsq[w0 + 3];
    float mu = s1 * (1.f / EMB);
    float var = s2 * (1.f / EMB) - mu * mu;
    float inv = rsqrtf(var + 1e-5f);

    float4 gg = reinterpret_cast<const float4*>(g)[t];
    float4 bb = reinterpret_cast<const float4*>(beta)[t];
    float4 y = make_float4((v.x - mu) * inv * gg.x + bb.x,
                           (v.y - mu) * inv * gg.y + bb.y,
                           (v.z - mu) * inv * gg.z + bb.z,
                           (v.w - mu) * inv * gg.w + bb.w);
    if (of) reinterpret_cast<float4*>(of)[(size_t)row * 128 + t] = y;
    if (oh) {
        __half2 h0 = __floats2half2_rn(y.x, y.y);
        __half2 h1 = __floats2half2_rn(y.z, y.w);
        uint2 pk = make_uint2(*reinterpret_cast<uint32_t*>(&h0), *reinterpret_cast<uint32_t*>(&h1));
        reinterpret_cast<uint2*>(oh)[(size_t)row * 128 + t] = pk;
    }
}

// ---------------------------------------------------------------------------
// Launch
// ---------------------------------------------------------------------------
extern "C" void kernel_launch(void* const* d_in, const int* in_sizes, int n_in,
                              void* d_out, int out_size)
{
    (void)in_sizes; (void)n_in; (void)out_size;

    const float* x_in = (const float*)d_in[0];
    const float* qW1 = (const float*)d_in[1];  const float* qb1 = (const float*)d_in[2];
    const float* qW2 = (const float*)d_in[3];  const float* qb2 = (const float*)d_in[4];
    const float* kW1 = (const float*)d_in[5];  const float* kb1 = (const float*)d_in[6];
    const float* kW2 = (const float*)d_in[7];  const float* kb2 = (const float*)d_in[8];
    const float* vW1 = (const float*)d_in[9];  const float* vb1 = (const float*)d_in[10];
    const float* vW2 = (const float*)d_in[11]; const float* vb2 = (const float*)d_in[12];
    const float* fW1 = (const float*)d_in[13]; const float* fb1 = (const float*)d_in[14];
    const float* fW2 = (const float*)d_in[15]; const float* fb2 = (const float*)d_in[16];
    const float* ln1g = (const float*)d_in[17]; const float* ln1b = (const float*)d_in[18];
    const float* ln2g = (const float*)d_in[19]; const float* ln2b = (const float*)d_in[20];
    float* out = (float*)d_out;

    float *pb1c, *pb2c;
    cudaGetSymbolAddress((void**)&pb1c, g_b1cat);
    cudaGetSymbolAddress((void**)&pb2c, g_b2cat);
    __half *xh, *hidh, *qkvh, *ctx16, *ah, *bh;
    cudaGetSymbolAddress((void**)&xh, g_xh);
    cudaGetSymbolAddress((void**)&hidh, g_hidh);
    cudaGetSymbolAddress((void**)&qkvh, g_qkvh);
    cudaGetSymbolAddress((void**)&ctx16, g_ctx16);
    cudaGetSymbolAddress((void**)&ah, g_ah);
    cudaGetSymbolAddress((void**)&bh, g_bh);
    __half *w1h, *w2h, *f1h, *f2h;
    cudaGetSymbolAddress((void**)&w1h, g_w1h);
    cudaGetSymbolAddress((void**)&w2h, g_w2h);
    cudaGetSymbolAddress((void**)&f1h, g_f1h);
    cudaGetSymbolAddress((void**)&f2h, g_f2h);

    __half* ff16 = hidh;

    cudaFuncSetAttribute(hmma_gemm, cudaFuncAttributeMaxDynamicSharedMemorySize, GSMEM);
    cudaFuncSetAttribute(flash_hmma, cudaFuncAttributeMaxDynamicSharedMemorySize, FSMEM);

    // One prep launch (transpose + x convert + biases)
    prep_all<<<2176 + XB, 256>>>(x_in, qW1, kW1, vW1, qW2, kW2, vW2, fW1, fW2,
                                 qb1, kb1, vb1, qb2, kb2, vb2,
                                 w1h, w2h, f1h, f2h, xh, pb1c, pb2c);

    // Merged QKV layer-1
    hmma_gemm<<<dim3(12, 64), 256, GSMEM>>>(xh, 256, 0, w1h, pb1c, hidh, 1536, 256, 1);
    // Merged QKV layer-2 -> qkv fp16
    hmma_gemm<<<dim3(12, 64), 256, GSMEM>>>(hidh, 1536, 512, w2h, pb2c, qkvh, 1536, 512, 0);

    // Attention -> ctx16
    flash_hmma<<<dim3(SEQ / 64, 8, 4), 128, FSMEM>>>(qkvh, ctx16);

    // x = LN(ctx + q) -> bh
    ln16<<<TOK / 2, 256>>>(ctx16, 512, qkvh, 1536, ln1g, ln1b, bh, (float*)nullptr);

    // FFN
    hmma_gemm<<<dim3(8, 64), 256, GSMEM>>>(bh, 512, 0, f1h, fb1, ah, 1024, 512, 1);
    hmma_gemm<<<dim3(4, 64), 256, GSMEM>>>(ah, 1024, 0, f2h, fb2, ff16, 512, 1024, 0);

    // out = LN(ff + x)
    ln16<<<TOK / 2, 256>>>(ff16, 512, bh, 512, ln2g, ln2b, (__half*)nullptr, out);
}